// round 15
// baseline (speedup 1.0000x reference)
#include <cuda_runtime.h>
#include <cuda_fp16.h>
#include <math.h>
#include <stdint.h>

// ---------------- problem constants ----------------
#define BB   8
#define NN   2049
#define CC   768
#define HH   12
#define NBB  4
#define HD   64
#define SPB  512
#define MROWS (BB*NN)      // 16392
#define MPAD  16512        // 129 * 128
#define SCALE 0.125f
#define SCALE2 0.18033688011112042f   // SCALE * log2(e)
#define LNEPS 1e-6f
#define NSPLIT 16
#define CHUNK 129          // ceil(2049/16)

// ---------------- scratch ----------------
__device__ float g_h1f [(size_t)MROWS * CC];       // only cls rows written/read
__device__ __half g_h1h[(size_t)MPAD * CC];
__device__ __half g_qkvh[(size_t)MROWS * 3 * CC];
__device__ __half g_qkvch[BB * 3 * CC];
__device__ float g_cls [BB * CC];
__device__ float g_clsp[BB * HH * NSPLIT * 80];    // partial m,l,o[64]
__device__ __half g_yh [(size_t)MPAD * CC];
__device__ float g_x2  [(size_t)MROWS * CC];
__device__ __half g_h2h[(size_t)MPAD * CC];
__device__ __half g_f1h[(size_t)MPAD * 4 * CC];
__device__ __half g_wqh[3*CC*CC];
__device__ __half g_wph[CC*CC];
__device__ __half g_w1h[4*CC*CC];
__device__ __half g_w2h[4*CC*CC];

// ---------------- helpers ----------------
__device__ __forceinline__ uint32_t smem_u32(const void* p) {
    return (uint32_t)__cvta_generic_to_shared(p);
}
__device__ __forceinline__ void cp16(uint32_t saddr, const void* g) {
    asm volatile("cp.async.cg.shared.global [%0], [%1], 16;\n" :: "r"(saddr), "l"(g));
}
__device__ __forceinline__ void cp_commit() { asm volatile("cp.async.commit_group;\n"); }
template<int NW> __device__ __forceinline__ void cp_wait() {
    asm volatile("cp.async.wait_group %0;\n" :: "n"(NW));
}
__device__ __forceinline__ void ldsm4(uint32_t addr, uint32_t& r0, uint32_t& r1,
                                      uint32_t& r2, uint32_t& r3) {
    asm volatile("ldmatrix.sync.aligned.m8n8.x4.shared.b16 {%0,%1,%2,%3}, [%4];"
                 : "=r"(r0), "=r"(r1), "=r"(r2), "=r"(r3) : "r"(addr));
}
__device__ __forceinline__ void ldsm4t(uint32_t addr, uint32_t& r0, uint32_t& r1,
                                       uint32_t& r2, uint32_t& r3) {
    asm volatile("ldmatrix.sync.aligned.m8n8.x4.trans.shared.b16 {%0,%1,%2,%3}, [%4];"
                 : "=r"(r0), "=r"(r1), "=r"(r2), "=r"(r3) : "r"(addr));
}
__device__ __forceinline__ void mma16816(float* c, const uint32_t* a, const uint32_t* b) {
    asm volatile("mma.sync.aligned.m16n8k16.row.col.f32.f16.f16.f32 "
        "{%0,%1,%2,%3}, {%4,%5,%6,%7}, {%8,%9}, {%0,%1,%2,%3};"
        : "+f"(c[0]), "+f"(c[1]), "+f"(c[2]), "+f"(c[3])
        : "r"(a[0]), "r"(a[1]), "r"(a[2]), "r"(a[3]), "r"(b[0]), "r"(b[1]));
}
__device__ __forceinline__ uint32_t pack2h(float a, float b) {
    __half2 h = __float22half2_rn(make_float2(a, b));
    return *(uint32_t*)&h;
}

// ---------------- LN row body (warp-collective) ----------------
__device__ __forceinline__ void ln_row(const float* __restrict__ x,
                                       const float* __restrict__ w,
                                       const float* __restrict__ b,
                                       float* __restrict__ outf,
                                       __half* __restrict__ oh,
                                       int row, int lane)
{
    const float4* xr = (const float4*)(x + (size_t)row * CC);

    float4 v[6];
    float s = 0.0f;
    #pragma unroll
    for (int i = 0; i < 6; i++) {
        v[i] = xr[i * 32 + lane];
        s += v[i].x + v[i].y + v[i].z + v[i].w;
    }
    #pragma unroll
    for (int o = 16; o; o >>= 1) s += __shfl_xor_sync(0xffffffffu, s, o);
    float mu = s * (1.0f / CC);

    float q = 0.0f;
    #pragma unroll
    for (int i = 0; i < 6; i++) {
        v[i].x -= mu; v[i].y -= mu; v[i].z -= mu; v[i].w -= mu;
        q += v[i].x*v[i].x + v[i].y*v[i].y + v[i].z*v[i].z + v[i].w*v[i].w;
    }
    #pragma unroll
    for (int o = 16; o; o >>= 1) q += __shfl_xor_sync(0xffffffffu, q, o);
    float rs = rsqrtf(q * (1.0f / CC) + LNEPS);

    const float4* w4 = (const float4*)w;
    const float4* b4 = (const float4*)b;
    uint2* oh2 = (uint2*)(oh + (size_t)row * CC);
    bool wf = (outf != nullptr) && (row % NN) == 0;
    float4* of4 = wf ? (float4*)(outf + (size_t)row * CC) : nullptr;

    #pragma unroll
    for (int i = 0; i < 6; i++) {
        float4 wv = w4[i * 32 + lane], bv = b4[i * 32 + lane];
        float o0 = v[i].x * rs * wv.x + bv.x;
        float o1 = v[i].y * rs * wv.y + bv.y;
        float o2 = v[i].z * rs * wv.z + bv.z;
        float o3 = v[i].w * rs * wv.w + bv.w;
        oh2[i * 32 + lane] = make_uint2(pack2h(o0, o1), pack2h(o2, o3));
        if (wf) of4[i * 32 + lane] = make_float4(o0, o1, o2, o3);
    }
}

// ---------------- prologue: LN1 blocks + weight-convert blocks in ONE launch ---
__global__ void __launch_bounds__(256) prologue_kernel(
    const float* __restrict__ x, const float* __restrict__ ln1_w,
    const float* __restrict__ ln1_b, float* __restrict__ h1f,
    __half* __restrict__ h1h, int ln_blocks,
    const float* __restrict__ i0, const float* __restrict__ i1,
    const float* __restrict__ i2, const float* __restrict__ i3,
    __half* __restrict__ o0, __half* __restrict__ o1,
    __half* __restrict__ o2, __half* __restrict__ o3,
    int c1, int c2, int c3)
{
    int bi = blockIdx.x;
    if (bi < ln_blocks) {
        int row = bi * 8 + (threadIdx.x >> 5);
        if (row < MROWS)
            ln_row(x, ln1_w, ln1_b, h1f, h1h, row, threadIdx.x & 31);
    } else {
        int cb = bi - ln_blocks;
        const float* in; __half* oh; int base;
        if (cb < c1)      { in = i0; oh = o0; base = 0;  }
        else if (cb < c2) { in = i1; oh = o1; base = c1; }
        else if (cb < c3) { in = i2; oh = o2; base = c2; }
        else              { in = i3; oh = o3; base = c3; }
        int i = (cb - base) * 256 + threadIdx.x;
        float4 v = ((const float4*)in)[i];
        uint2 o;
        o.x = pack2h(v.x, v.y);
        o.y = pack2h(v.z, v.w);
        ((uint2*)oh)[i] = o;
    }
}

// ---------------- LN2 (standalone) ----------------
__global__ void __launch_bounds__(256) ln_kernel(const float* __restrict__ x,
                                                 const float* __restrict__ w,
                                                 const float* __restrict__ b,
                                                 __half* __restrict__ oh,
                                                 int rows)
{
    int row = blockIdx.x * 8 + (threadIdx.x >> 5);
    if (row >= rows) return;
    ln_row(x, w, b, nullptr, oh, row, threadIdx.x & 31);
}

// ================= single-pass fp16 mma.sync GEMM =================
#define TILE_B   16384
#define NSTAGE   3

template<int EPI, int OUTM>
__global__ void __launch_bounds__(256, 2) tc_gemm(
    const __half* __restrict__ Ah, const __half* __restrict__ Wh,
    const float* __restrict__ bias, const float* __restrict__ res,
    float* __restrict__ Cf, __half* __restrict__ Ch,
    int M, int N, int K)
{
    constexpr uint32_t STB = 2 * TILE_B;

    extern __shared__ char dynraw[];
    uint32_t raw = smem_u32(dynraw);
    uint32_t smb = (raw + 127) & ~127u;

    const int tid = threadIdx.x;
    const int bn = blockIdx.x * 128, bm = blockIdx.y * 128;
    const int nt = K >> 6;
    const int lane = tid & 31, wid = tid >> 5;
    const int wm = (wid & 1) * 64, wn = (wid >> 1) * 32;
    const int r8 = lane & 7, sub = lane >> 3;

    const int lrow = tid >> 1;
    const int c0 = (tid & 1) * 4;

    auto load_stage = [&](int kt, int s) {
        uint32_t sb = smb + s * STB;
        size_t goff = (size_t)(kt * 64 + c0 * 8);
        const __half* gAh = Ah + (size_t)(bm + lrow) * K + goff;
        const __half* gWh = Wh + (size_t)(bn + lrow) * K + goff;
        uint32_t ro = lrow * 128;
        #pragma unroll
        for (int c = 0; c < 4; c++) {
            int chunk = c0 + c;
            uint32_t sw = ro + (uint32_t)((chunk ^ (lrow & 7)) << 4);
            cp16(sb          + sw, gAh + c*8);
            cp16(sb + TILE_B + sw, gWh + c*8);
        }
        cp_commit();
    };

    float acc[4][4][4];
    #pragma unroll
    for (int i = 0; i < 4; i++)
        #pragma unroll
        for (int j = 0; j < 4; j++)
            #pragma unroll
            for (int t = 0; t < 4; t++) acc[i][j][t] = 0.0f;

    uint32_t aRowBase[4]; int aKey[4];
    #pragma unroll
    for (int mi = 0; mi < 4; mi++) {
        int row = wm + mi*16 + ((sub & 1) << 3) + r8;
        aRowBase[mi] = row * 128;
        aKey[mi] = row & 7;
    }
    const int aChunkOff = sub >> 1;
    uint32_t bRowBase[2]; int bKey[2];
    #pragma unroll
    for (int pr = 0; pr < 2; pr++) {
        int row = wn + pr*16 + ((sub >> 1) << 3) + r8;
        bRowBase[pr] = row * 128;
        bKey[pr] = row & 7;
    }
    const int bChunkOff = sub & 1;

    load_stage(0, 0);
    load_stage(1, 1);

    for (int kt = 0; kt < nt; kt++) {
        if (kt + 1 < nt) cp_wait<1>(); else cp_wait<0>();
        __syncthreads();
        if (kt + 2 < nt) load_stage(kt + 2, (kt + 2) % NSTAGE);

        uint32_t sb = smb + (kt % NSTAGE) * STB;

        #pragma unroll
        for (int kk = 0; kk < 4; kk++) {
            uint32_t Bh[2][4];
            #pragma unroll
            for (int pr = 0; pr < 2; pr++) {
                int chunk = kk*2 + bChunkOff;
                uint32_t ad = sb + TILE_B + bRowBase[pr]
                            + (uint32_t)((chunk ^ bKey[pr]) << 4);
                ldsm4(ad, Bh[pr][0], Bh[pr][1], Bh[pr][2], Bh[pr][3]);
            }
            #pragma unroll
            for (int mi = 0; mi < 4; mi++) {
                int chunk = kk*2 + aChunkOff;
                uint32_t ad = sb + aRowBase[mi]
                            + (uint32_t)((chunk ^ aKey[mi]) << 4);
                uint32_t Af[4];
                ldsm4(ad, Af[0], Af[1], Af[2], Af[3]);
                #pragma unroll
                for (int ni = 0; ni < 4; ni++) {
                    int pr = ni >> 1, half = (ni & 1) * 2;
                    mma16816(acc[mi][ni], Af, &Bh[pr][half]);
                }
            }
        }
    }

    // ---- epilogue: vectorized (float2 / half2) ----
    int r4 = lane >> 2, c2 = (lane & 3) * 2;
    #pragma unroll
    for (int mi = 0; mi < 4; mi++) {
        #pragma unroll
        for (int hh = 0; hh < 2; hh++) {
            int m = bm + wm + mi*16 + r4 + hh*8;
            if (m >= M) continue;
            #pragma unroll
            for (int ni = 0; ni < 4; ni++) {
                int n0 = bn + wn + ni*8 + c2;
                float v0 = acc[mi][ni][hh*2 + 0];
                float v1 = acc[mi][ni][hh*2 + 1];
                size_t idx = (size_t)m * N + n0;
                if (EPI != 0) {
                    float2 bb = *(const float2*)&bias[n0];
                    v0 += bb.x; v1 += bb.y;
                }
                if (EPI == 1) {
                    float2 rr = *(const float2*)&res[idx];
                    v0 += rr.x; v1 += rr.y;
                }
                if (EPI == 2) {
                    v0 = 0.5f * v0 * (1.0f + erff(v0 * 0.7071067811865476f));
                    v1 = 0.5f * v1 * (1.0f + erff(v1 * 0.7071067811865476f));
                }
                if (OUTM == 0) *(float2*)&Cf[idx] = make_float2(v0, v1);
                else           *(uint32_t*)&Ch[idx] = pack2h(v0, v1);
            }
        }
    }
}

// ---------------- cls attention, split-K partials (coalesced QK, exp2 domain) ---
__global__ void __launch_bounds__(256) cls_attn_part(const __half* __restrict__ qkvh,
                                                     float* __restrict__ part)
{
    __shared__ float sq[64];
    __shared__ float sc[CHUNK];
    __shared__ float red[256];
    __shared__ float so[4][64];

    int bh = blockIdx.x, sp = blockIdx.y;
    int b = bh / HH, h = bh % HH;
    int tid = threadIdx.x;
    int lane = tid & 31, wid = tid >> 5;
    int i0 = sp * CHUNK;
    int i1 = i0 + CHUNK; if (i1 > NN) i1 = NN;
    int cnt = i1 - i0;

    const __half* qbase = qkvh + (size_t)(b * NN) * (3*CC) + h * HD;
    if (tid < 64) sq[tid] = __half2float(qbase[tid]);
    __syncthreads();

    const int g = lane >> 3;
    const int s8 = lane & 7;
    float qf[8];
    #pragma unroll
    for (int i = 0; i < 8; i++) qf[i] = sq[s8 * 8 + i];

    float lmax = -1e30f;
    for (int base = 0; base < cnt; base += 32) {
        int j = base + wid * 4 + g;
        float dot = 0.0f;
        if (j < cnt) {
            const uint4* kr = (const uint4*)(qkvh + (size_t)(b * NN + i0 + j) * (3*CC) + CC + h * HD);
            uint4 kv = kr[s8];
            __half2 h0 = *(__half2*)&kv.x, h1v = *(__half2*)&kv.y;
            __half2 h2 = *(__half2*)&kv.z, h3 = *(__half2*)&kv.w;
            float2 f0 = __half22float2(h0), f1 = __half22float2(h1v);
            float2 f2 = __half22float2(h2), f3 = __half22float2(h3);
            dot = qf[0]*f0.x + qf[1]*f0.y + qf[2]*f1.x + qf[3]*f1.y
                + qf[4]*f2.x + qf[5]*f2.y + qf[6]*f3.x + qf[7]*f3.y;
        }
        dot += __shfl_xor_sync(0xffffffffu, dot, 1);
        dot += __shfl_xor_sync(0xffffffffu, dot, 2);
        dot += __shfl_xor_sync(0xffffffffu, dot, 4);
        if (s8 == 0 && j < cnt) {
            float sv = dot * SCALE2;
            sc[j] = sv;
            lmax = fmaxf(lmax, sv);
        }
    }
    red[tid] = lmax; __syncthreads();
    for (int off = 128; off; off >>= 1) {
        if (tid < off) red[tid] = fmaxf(red[tid], red[tid + off]);
        __syncthreads();
    }
    float m = red[0];
    __syncthreads();

    float lsum = 0.0f;
    for (int j = tid; j < cnt; j += 256) {
        float e = exp2f(sc[j] - m);
        sc[j] = e;
        lsum += e;
    }
    red[tid] = lsum; __syncthreads();
    for (int off = 128; off; off >>= 1) {
        if (tid < off) red[tid] += red[tid + off];
        __syncthreads();
    }
    float l = red[0];
    __syncthreads();

    int d = tid & 63, p = tid >> 6;
    float o = 0.0f;
    for (int j = p; j < cnt; j += 4)
        o = fmaf(sc[j], __half2float(qkvh[(size_t)(b * NN + i0 + j) * (3*CC) + 2*CC + h * HD + d]), o);
    so[p][d] = o;
    __syncthreads();

    float* pr = part + (size_t)(bh * NSPLIT + sp) * 80;
    if (tid == 0) { pr[0] = m; pr[1] = l; }
    if (tid < 64) pr[2 + tid] = so[0][tid] + so[1][tid] + so[2][tid] + so[3][tid];
}

// ---------------- cls attention reduce (exp2 domain) ----------------
__global__ void __launch_bounds__(64) cls_attn_reduce(const float* __restrict__ part,
                                                      const float* __restrict__ h1,
                                                      float* __restrict__ cls,
                                                      __half* __restrict__ yh)
{
    int bh = blockIdx.x;
    int b = bh / HH, h = bh % HH;
    int d = threadIdx.x;

    const float* pr = part + (size_t)bh * NSPLIT * 80;
    float m = -1e30f;
    #pragma unroll
    for (int s = 0; s < NSPLIT; s++) m = fmaxf(m, pr[s*80]);
    float l = 0.0f, o = 0.0f;
    #pragma unroll
    for (int s = 0; s < NSPLIT; s++) {
        float w = exp2f(pr[s*80] - m);
        l += w * pr[s*80 + 1];
        o += w * pr[s*80 + 2 + d];
    }
    float val = o / l;
    size_t off0 = (size_t)(b * NN) * CC + h * HD + d;
    float v = val + h1[off0];
    cls[b * CC + h * HD + d] = v;
    yh[off0] = __float2half_rn(v);
}

// ---------------- cls qkv (fp16 weights, vectorized) ----------------
__global__ void __launch_bounds__(256) cls_qkv_kernel(const float* __restrict__ cls,
                                                      const __half* __restrict__ wqh,
                                                      __half* __restrict__ qkvch)
{
    int j = blockIdx.x;
    int w = threadIdx.x >> 5;
    int lane = threadIdx.x & 31;
    const float2* cr = (const float2*)(cls + (size_t)w * CC);
    const __half2* wr = (const __half2*)(wqh + (size_t)j * CC);
    float s = 0.0f;
    #pragma unroll 4
    for (int k = lane; k < CC/2; k += 32) {
        float2 c = cr[k];
        float2 wv = __half22float2(wr[k]);
        s = fmaf(c.x, wv.x, s);
        s = fmaf(c.y, wv.y, s);
    }
    #pragma unroll
    for (int off = 16; off; off >>= 1) s += __shfl_xor_sync(0xffffffffu, s, off);
    if (lane == 0) qkvch[w * (3*CC) + j] = __float2half_rn(s);
}

// ---------------- branch attention: 256-query tiles, 16 warps, 3-buffer KV ring --
// smem: Q 32KB + 3 x 16KB KV = 80KB. grid (2, NBB, 96) = 768 CTAs.
#define BQ   0
#define BKV  32768

__global__ void __launch_bounds__(512) branch_attn_kernel(
    const __half* __restrict__ qkvh, const __half* __restrict__ qkvch,
    __half* __restrict__ yh)
{
    extern __shared__ char dynraw[];
    uint32_t raw = smem_u32(dynraw);
    uint32_t smb = (raw + 127) & ~127u;

    const int tid = threadIdx.x;
    const int lane = tid & 31, wid = tid >> 5;       // 16 warps
    const int r8 = lane & 7, sub = lane >> 3;
    const int qt = blockIdx.x, nb = blockIdx.y;      // qt 0..1 (256 queries each)
    const int b = blockIdx.z / HH, h = blockIdx.z % HH;

    // KV loaders: 8 threads/row, 1 chunk each (64 rows x 8 chunks = 512 threads)
    const int kr = tid >> 3;
    const int kch = tid & 7;
    const uint32_t kro = kr * 128;

    auto load_kv = [&](int kt, int buf) {
        int jg = kt * 64 + kr;
        int jc = jg > 512 ? 512 : jg;
        const __half *kh_s, *vh_s;
        if (jc == 0) {
            size_t rb = (size_t)b * (3*CC) + h * HD;
            kh_s = qkvch + rb + CC;
            vh_s = qkvch + rb + 2*CC;
        } else {
            int token = nb * SPB + jc;
            size_t rb = (size_t)(b * NN + token) * (3*CC) + h * HD;
            kh_s = qkvh + rb + CC;
            vh_s = qkvh + rb + 2*CC;
        }
        uint32_t bk = smb + BKV + buf * 16384;
        uint32_t bv = bk + 8192;
        uint32_t sw = kro + (uint32_t)((kch ^ (kr & 7)) << 4);
        cp16(bk + sw, kh_s + kch*8);
        cp16(bv + sw, vh_s + kch*8);
        cp_commit();
    };

    // ---- load Q tile (256 rows, 2 threads/row, 4 chunks) ----
    {
        int qrow = tid >> 1;
        int ch0 = (tid & 1) * 4;
        int token = 1 + nb * SPB + qt * 256 + qrow;
        const __half* gh = qkvh + (size_t)(b * NN + token) * (3*CC) + h * HD;
        uint32_t ro = qrow * 128;
        #pragma unroll
        for (int c = 0; c < 4; c++) {
            int chunk = ch0 + c;
            uint32_t sw = ro + (uint32_t)((chunk ^ (qrow & 7)) << 4);
            cp16(smb + BQ + sw, gh + chunk*8);
        }
        cp_commit();
    }
    load_kv(0, 0);
    load_kv(1, 1);

    float m0 = -1e30f, m1 = -1e30f, l0 = 0.0f, l1 = 0.0f;
    float oreg[8][4];
    #pragma unroll
    for (int i = 0; i < 8; i++)
        #pragma unroll
        for (int t = 0; t < 4; t++) oreg[i][t] = 0.0f;

    for (int kt = 0; kt < 9; kt++) {
        if (kt < 8) cp_wait<1>(); else cp_wait<0>();
        __syncthreads();
        if (kt + 2 < 9) load_kv(kt + 2, (kt + 2) % 3);

        uint32_t bk = smb + BKV + (kt % 3) * 16384;
        uint32_t bv = bk + 8192;

        // ---- S = Q K^T ----
        float sreg[8][4];
        #pragma unroll
        for (int i = 0; i < 8; i++)
            #pragma unroll
            for (int t = 0; t < 4; t++) sreg[i][t] = 0.0f;

        #pragma unroll
        for (int kk = 0; kk < 4; kk++) {
            int arow = wid*16 + ((sub & 1) << 3) + r8;
            uint32_t aad = smb + BQ + arow*128
                         + (uint32_t)(((kk*2 + (sub >> 1)) ^ (arow & 7)) << 4);
            uint32_t qh[4];
            ldsm4(aad, qh[0], qh[1], qh[2], qh[3]);
            #pragma unroll
            for (int pr = 0; pr < 4; pr++) {
                int brow = pr*16 + ((sub >> 1) << 3) + r8;
                uint32_t bad = bk + brow*128
                             + (uint32_t)(((kk*2 + (sub & 1)) ^ (brow & 7)) << 4);
                uint32_t kh[4];
                ldsm4(bad, kh[0], kh[1], kh[2], kh[3]);
                mma16816(sreg[pr*2    ], qh, &kh[0]);
                mma16816(sreg[pr*2 + 1], qh, &kh[2]);
            }
        }

        // ---- scale (log2 domain) + mask ----
        #pragma unroll
        for (int nt = 0; nt < 8; nt++)
            #pragma unroll
            for (int t = 0; t < 4; t++) {
                float v = sreg[nt][t] * SCALE2;
                int gcol = kt*64 + nt*8 + (lane & 3)*2 + (t & 1);
                if (gcol > 512) v = -1e30f;
                sreg[nt][t] = v;
            }

        float mt0 = -1e30f, mt1 = -1e30f;
        #pragma unroll
        for (int nt = 0; nt < 8; nt++) {
            mt0 = fmaxf(mt0, fmaxf(sreg[nt][0], sreg[nt][1]));
            mt1 = fmaxf(mt1, fmaxf(sreg[nt][2], sreg[nt][3]));
        }
        mt0 = fmaxf(mt0, __shfl_xor_sync(0xffffffffu, mt0, 1));
        mt0 = fmaxf(mt0, __shfl_xor_sync(0xffffffffu, mt0, 2));
        mt1 = fmaxf(mt1, __shfl_xor_sync(0xffffffffu, mt1, 1));
        mt1 = fmaxf(mt1, __shfl_xor_sync(0xffffffffu, mt1, 2));
        float mn0 = fmaxf(m0, mt0), mn1 = fmaxf(m1, mt1);
        float a0 = exp2f(m0 - mn0), a1 = exp2f(m1 - mn1);
        m0 = mn0; m1 = mn1;
        float rs0 = 0.0f, rs1 = 0.0f;
        #pragma unroll
        for (int nt = 0; nt < 8; nt++) {
            sreg[nt][0] = exp2f(sreg[nt][0] - mn0);
            sreg[nt][1] = exp2f(sreg[nt][1] - mn0);
            sreg[nt][2] = exp2f(sreg[nt][2] - mn1);
            sreg[nt][3] = exp2f(sreg[nt][3] - mn1);
            rs0 += sreg[nt][0] + sreg[nt][1];
            rs1 += sreg[nt][2] + sreg[nt][3];
        }
        rs0 += __shfl_xor_sync(0xffffffffu, rs0, 1);
        rs0 += __shfl_xor_sync(0xffffffffu, rs0, 2);
        rs1 += __shfl_xor_sync(0xffffffffu, rs1, 1);
        rs1 += __shfl_xor_sync(0xffffffffu, rs1, 2);
        l0 = l0 * a0 + rs0;
        l1 = l1 * a1 + rs1;
        #pragma unroll
        for (int dt = 0; dt < 8; dt++) {
            oreg[dt][0] *= a0; oreg[dt][1] *= a0;
            oreg[dt][2] *= a1; oreg[dt][3] *= a1;
        }

        uint32_t ph[4][4];
        #pragma unroll
        for (int kc = 0; kc < 4; kc++) {
            ph[kc][0] = pack2h(sreg[2*kc][0],   sreg[2*kc][1]);
            ph[kc][1] = pack2h(sreg[2*kc][2],   sreg[2*kc][3]);
            ph[kc][2] = pack2h(sreg[2*kc+1][0], sreg[2*kc+1][1]);
            ph[kc][3] = pack2h(sreg[2*kc+1][2], sreg[2*kc+1][3]);
        }

        #pragma unroll
        for (int kc = 0; kc < 4; kc++) {
            #pragma unroll
            for (int dg = 0; dg < 4; dg++) {
                int vrow = kc*16 + ((sub & 1) << 3) + r8;
                uint32_t vad = bv + vrow*128
                             + (uint32_t)(((dg*2 + (sub >> 1)) ^ (vrow & 7)) << 4);
                uint32_t vh[4];
                ldsm4t(vad, vh[0], vh[1], vh[2], vh[3]);
                mma16816(oreg[dg*2    ], ph[kc], &vh[0]);
                mma16816(oreg[dg*2 + 1], ph[kc], &vh[2]);
            }
        }
    }

    // ---- write out (scrambled reshape, half2-paired stores) ----
    float inv0 = 1.0f / l0, inv1 = 1.0f / l1;
    int r4 = lane >> 2, c2 = (lane & 3) * 2;
    #pragma unroll
    for (int dt = 0; dt < 8; dt++) {
        #pragma unroll
        for (int rh = 0; rh < 2; rh++) {
            int sp = qt*256 + wid*16 + r4 + rh*8;
            int dp = dt*8 + c2;
            float inv = rh ? inv1 : inv0;
            float v0 = oreg[dt][rh*2 + 0] * inv;
            float v1 = oreg[dt][rh*2 + 1] * inv;
            int linear = h * (SPB * HD) + sp * HD + dp;   // even
            int s_ = linear / CC;
            int c = linear - s_ * CC;
            int token = 1 + nb * SPB + s_;
            *(uint32_t*)&yh[(size_t)(b * NN + token) * CC + c] = pack2h(v0, v1);
        }
    }
}

// ---------------- launch ----------------
extern "C" void kernel_launch(void* const* d_in, const int* in_sizes, int n_in,
                              void* d_out, int out_size)
{
    const float* x      = (const float*)d_in[0];
    const float* ln1_w  = (const float*)d_in[1];
    const float* ln1_b  = (const float*)d_in[2];
    const float* qkv_w  = (const float*)d_in[3];
    const float* proj_w = (const float*)d_in[4];
    const float* proj_b = (const float*)d_in[5];
    const float* ln2_w  = (const float*)d_in[6];
    const float* ln2_b  = (const float*)d_in[7];
    const float* fc1_w  = (const float*)d_in[8];
    const float* fc1_b  = (const float*)d_in[9];
    const float* fc2_w  = (const float*)d_in[10];
    const float* fc2_b  = (const float*)d_in[11];
    float* out = (float*)d_out;

    float *h1f, *cls, *clsp, *x2;
    __half *h1h, *qkvh, *qkvch, *yh, *h2h, *f1h;
    __half *wqh, *wph, *w1h, *w2h;
    cudaGetSymbolAddress((void**)&h1f,   g_h1f);
    cudaGetSymbolAddress((void**)&h1h,   g_h1h);
    cudaGetSymbolAddress((void**)&qkvh,  g_qkvh);
    cudaGetSymbolAddress((void**)&qkvch, g_qkvch);
    cudaGetSymbolAddress((void**)&cls,   g_cls);
    cudaGetSymbolAddress((void**)&clsp,  g_clsp);
    cudaGetSymbolAddress((void**)&yh,    g_yh);
    cudaGetSymbolAddress((void**)&x2,    g_x2);
    cudaGetSymbolAddress((void**)&h2h,   g_h2h);
    cudaGetSymbolAddress((void**)&f1h,   g_f1h);
    cudaGetSymbolAddress((void**)&wqh,   g_wqh);
    cudaGetSymbolAddress((void**)&wph,   g_wph);
    cudaGetSymbolAddress((void**)&w1h,   g_w1h);
    cudaGetSymbolAddress((void**)&w2h,   g_w2h);

    const int M = MROWS;
    const int smem1 = NSTAGE * 2 * TILE_B + 128;   // 98432
    cudaFuncSetAttribute(tc_gemm<0,3>, cudaFuncAttributeMaxDynamicSharedMemorySize, smem1);
    cudaFuncSetAttribute(tc_gemm<1,0>, cudaFuncAttributeMaxDynamicSharedMemorySize, smem1);
    cudaFuncSetAttribute(tc_gemm<2,3>, cudaFuncAttributeMaxDynamicSharedMemorySize, smem1);
    const int ba_smem = 32768 + 3*16384 + 128;     // Q(256) + 3x(K,V) = 80KB+pad
    cudaFuncSetAttribute(branch_attn_kernel, cudaFuncAttributeMaxDynamicSharedMemorySize, ba_smem);

    // 0+1. prologue: LN1 blocks + all weight converts, ONE launch
    {
        int ln_blocks = (M + 7) / 8;               // 2049
        int nb0 = 3*CC*CC/4/256;                   // 1728
        int nb1 = CC*CC/4/256;                     // 576
        int nb2 = 4*CC*CC/4/256;                   // 2304
        int nb3 = nb2;
        int c1 = nb0, c2 = nb0+nb1, c3 = nb0+nb1+nb2;
        prologue_kernel<<<ln_blocks + c3 + nb3, 256>>>(
            x, ln1_w, ln1_b, h1f, h1h, ln_blocks,
            qkv_w, proj_w, fc1_w, fc2_w, wqh, wph, w1h, w2h, c1, c2, c3);
    }

    // 2. qkv = h1 @ qkv_w^T  (fp16 out)
    {
        dim3 grid((3*CC)/128, MPAD/128);
        tc_gemm<0,3><<<grid, 256, smem1>>>(h1h, wqh, nullptr, nullptr,
                                           nullptr, qkvh, M, 3*CC, CC);
    }

    // 3. cls global attention (split-K partials + reduce)
    {
        dim3 grid(BB*HH, NSPLIT);
        cls_attn_part<<<grid, 256>>>(qkvh, clsp);
        cls_attn_reduce<<<BB*HH, 64>>>(clsp, h1f, cls, yh);
    }

    // 4. cls qkv (fp16 weights)
    cls_qkv_kernel<<<3*CC, 256>>>(cls, wqh, qkvch);

    // 5. branch attention (256-query tiles)
    {
        dim3 grid(2, NBB, BB*HH);
        branch_attn_kernel<<<grid, 512, ba_smem>>>(qkvh, qkvch, yh);
    }

    // 6. x2 = x + y @ proj_w^T + proj_b
    {
        dim3 grid(CC/128, MPAD/128);
        tc_gemm<1,0><<<grid, 256, smem1>>>(yh, wph, proj_b, x,
                                           x2, nullptr, M, CC, CC);
    }

    // 7. LN2 (fp16 out)
    ln_kernel<<<(M + 7)/8, 256>>>(x2, ln2_w, ln2_b, h2h, M);

    // 8. fc1 + gelu (fp16 out)
    {
        dim3 grid((4*CC)/128, MPAD/128);
        tc_gemm<2,3><<<grid, 256, smem1>>>(h2h, w1h, fc1_b, nullptr,
                                           nullptr, f1h, M, 4*CC, CC);
    }

    // 9. out = x2 + fc1g @ fc2_w^T + fc2_b
    {
        dim3 grid(CC/128, MPAD/128);
        tc_gemm<1,0><<<grid, 256, smem1>>>(f1h, w2h, fc2_b, x2,
                                           out, nullptr, M, CC, 4*CC);
    }
}

// round 16
// speedup vs baseline: 1.0159x; 1.0159x over previous
#include <cuda_runtime.h>
#include <cuda_fp16.h>
#include <math.h>
#include <stdint.h>

// ---------------- problem constants ----------------
#define BB   8
#define NN   2049
#define CC   768
#define HH   12
#define NBB  4
#define HD   64
#define SPB  512
#define MROWS (BB*NN)      // 16392
#define MPAD  16512        // 129 * 128
#define SCALE 0.125f
#define SCALE2 0.18033688011112042f   // SCALE * log2(e)
#define LNEPS 1e-6f
#define NSPLIT 16
#define CHUNK 129          // ceil(2049/16)

// ---------------- scratch ----------------
__device__ float g_h1f [(size_t)MROWS * CC];       // only cls rows written/read
__device__ __half g_h1h[(size_t)MPAD * CC];
__device__ __half g_qkvh[(size_t)MROWS * 3 * CC];
__device__ __half g_qkvch[BB * 3 * CC];
__device__ float g_cls [BB * CC];
__device__ float g_clsp[BB * HH * NSPLIT * 80];    // partial m,l,o[64]
__device__ __half g_yh [(size_t)MPAD * CC];
__device__ float g_x2  [(size_t)MROWS * CC];
__device__ __half g_h2h[(size_t)MPAD * CC];
__device__ __half g_f1h[(size_t)MPAD * 4 * CC];
__device__ __half g_wqh[3*CC*CC];
__device__ __half g_wph[CC*CC];
__device__ __half g_w1h[4*CC*CC];
__device__ __half g_w2h[4*CC*CC];

// ---------------- helpers ----------------
__device__ __forceinline__ uint32_t smem_u32(const void* p) {
    return (uint32_t)__cvta_generic_to_shared(p);
}
__device__ __forceinline__ void cp16(uint32_t saddr, const void* g) {
    asm volatile("cp.async.cg.shared.global [%0], [%1], 16;\n" :: "r"(saddr), "l"(g));
}
__device__ __forceinline__ void cp_commit() { asm volatile("cp.async.commit_group;\n"); }
template<int NW> __device__ __forceinline__ void cp_wait() {
    asm volatile("cp.async.wait_group %0;\n" :: "n"(NW));
}
__device__ __forceinline__ void ldsm4(uint32_t addr, uint32_t& r0, uint32_t& r1,
                                      uint32_t& r2, uint32_t& r3) {
    asm volatile("ldmatrix.sync.aligned.m8n8.x4.shared.b16 {%0,%1,%2,%3}, [%4];"
                 : "=r"(r0), "=r"(r1), "=r"(r2), "=r"(r3) : "r"(addr));
}
__device__ __forceinline__ void ldsm4t(uint32_t addr, uint32_t& r0, uint32_t& r1,
                                       uint32_t& r2, uint32_t& r3) {
    asm volatile("ldmatrix.sync.aligned.m8n8.x4.trans.shared.b16 {%0,%1,%2,%3}, [%4];"
                 : "=r"(r0), "=r"(r1), "=r"(r2), "=r"(r3) : "r"(addr));
}
__device__ __forceinline__ void mma16816(float* c, const uint32_t* a, const uint32_t* b) {
    asm volatile("mma.sync.aligned.m16n8k16.row.col.f32.f16.f16.f32 "
        "{%0,%1,%2,%3}, {%4,%5,%6,%7}, {%8,%9}, {%0,%1,%2,%3};"
        : "+f"(c[0]), "+f"(c[1]), "+f"(c[2]), "+f"(c[3])
        : "r"(a[0]), "r"(a[1]), "r"(a[2]), "r"(a[3]), "r"(b[0]), "r"(b[1]));
}
__device__ __forceinline__ uint32_t pack2h(float a, float b) {
    __half2 h = __float22half2_rn(make_float2(a, b));
    return *(uint32_t*)&h;
}

// ---------------- LN row body (warp-collective) ----------------
__device__ __forceinline__ void ln_row(const float* __restrict__ x,
                                       const float* __restrict__ w,
                                       const float* __restrict__ b,
                                       float* __restrict__ outf,
                                       __half* __restrict__ oh,
                                       int row, int lane)
{
    const float4* xr = (const float4*)(x + (size_t)row * CC);

    float4 v[6];
    float s = 0.0f;
    #pragma unroll
    for (int i = 0; i < 6; i++) {
        v[i] = xr[i * 32 + lane];
        s += v[i].x + v[i].y + v[i].z + v[i].w;
    }
    #pragma unroll
    for (int o = 16; o; o >>= 1) s += __shfl_xor_sync(0xffffffffu, s, o);
    float mu = s * (1.0f / CC);

    float q = 0.0f;
    #pragma unroll
    for (int i = 0; i < 6; i++) {
        v[i].x -= mu; v[i].y -= mu; v[i].z -= mu; v[i].w -= mu;
        q += v[i].x*v[i].x + v[i].y*v[i].y + v[i].z*v[i].z + v[i].w*v[i].w;
    }
    #pragma unroll
    for (int o = 16; o; o >>= 1) q += __shfl_xor_sync(0xffffffffu, q, o);
    float rs = rsqrtf(q * (1.0f / CC) + LNEPS);

    const float4* w4 = (const float4*)w;
    const float4* b4 = (const float4*)b;
    uint2* oh2 = (uint2*)(oh + (size_t)row * CC);
    bool wf = (outf != nullptr) && (row % NN) == 0;
    float4* of4 = wf ? (float4*)(outf + (size_t)row * CC) : nullptr;

    #pragma unroll
    for (int i = 0; i < 6; i++) {
        float4 wv = w4[i * 32 + lane], bv = b4[i * 32 + lane];
        float o0 = v[i].x * rs * wv.x + bv.x;
        float o1 = v[i].y * rs * wv.y + bv.y;
        float o2 = v[i].z * rs * wv.z + bv.z;
        float o3 = v[i].w * rs * wv.w + bv.w;
        oh2[i * 32 + lane] = make_uint2(pack2h(o0, o1), pack2h(o2, o3));
        if (wf) of4[i * 32 + lane] = make_float4(o0, o1, o2, o3);
    }
}

// ---------------- prologue: LN1 blocks + weight-convert blocks in ONE launch ---
__global__ void __launch_bounds__(256) prologue_kernel(
    const float* __restrict__ x, const float* __restrict__ ln1_w,
    const float* __restrict__ ln1_b, float* __restrict__ h1f,
    __half* __restrict__ h1h, int ln_blocks,
    const float* __restrict__ i0, const float* __restrict__ i1,
    const float* __restrict__ i2, const float* __restrict__ i3,
    __half* __restrict__ o0, __half* __restrict__ o1,
    __half* __restrict__ o2, __half* __restrict__ o3,
    int c1, int c2, int c3)
{
    int bi = blockIdx.x;
    if (bi < ln_blocks) {
        int row = bi * 8 + (threadIdx.x >> 5);
        if (row < MROWS)
            ln_row(x, ln1_w, ln1_b, h1f, h1h, row, threadIdx.x & 31);
    } else {
        int cb = bi - ln_blocks;
        const float* in; __half* oh; int base;
        if (cb < c1)      { in = i0; oh = o0; base = 0;  }
        else if (cb < c2) { in = i1; oh = o1; base = c1; }
        else if (cb < c3) { in = i2; oh = o2; base = c2; }
        else              { in = i3; oh = o3; base = c3; }
        int i = (cb - base) * 256 + threadIdx.x;
        float4 v = ((const float4*)in)[i];
        uint2 o;
        o.x = pack2h(v.x, v.y);
        o.y = pack2h(v.z, v.w);
        ((uint2*)oh)[i] = o;
    }
}

// ---------------- LN2 (standalone) ----------------
__global__ void __launch_bounds__(256) ln_kernel(const float* __restrict__ x,
                                                 const float* __restrict__ w,
                                                 const float* __restrict__ b,
                                                 __half* __restrict__ oh,
                                                 int rows)
{
    int row = blockIdx.x * 8 + (threadIdx.x >> 5);
    if (row >= rows) return;
    ln_row(x, w, b, nullptr, oh, row, threadIdx.x & 31);
}

// ================= single-pass fp16 mma.sync GEMM =================
#define TILE_B   16384
#define NSTAGE   3

template<int EPI, int OUTM>
__global__ void __launch_bounds__(256, 2) tc_gemm(
    const __half* __restrict__ Ah, const __half* __restrict__ Wh,
    const float* __restrict__ bias, const float* __restrict__ res,
    float* __restrict__ Cf, __half* __restrict__ Ch,
    int M, int N, int K)
{
    constexpr uint32_t STB = 2 * TILE_B;

    extern __shared__ char dynraw[];
    uint32_t raw = smem_u32(dynraw);
    uint32_t smb = (raw + 127) & ~127u;

    const int tid = threadIdx.x;
    const int bn = blockIdx.x * 128, bm = blockIdx.y * 128;
    const int nt = K >> 6;
    const int lane = tid & 31, wid = tid >> 5;
    const int wm = (wid & 1) * 64, wn = (wid >> 1) * 32;
    const int r8 = lane & 7, sub = lane >> 3;

    const int lrow = tid >> 1;
    const int c0 = (tid & 1) * 4;

    auto load_stage = [&](int kt, int s) {
        uint32_t sb = smb + s * STB;
        size_t goff = (size_t)(kt * 64 + c0 * 8);
        const __half* gAh = Ah + (size_t)(bm + lrow) * K + goff;
        const __half* gWh = Wh + (size_t)(bn + lrow) * K + goff;
        uint32_t ro = lrow * 128;
        #pragma unroll
        for (int c = 0; c < 4; c++) {
            int chunk = c0 + c;
            uint32_t sw = ro + (uint32_t)((chunk ^ (lrow & 7)) << 4);
            cp16(sb          + sw, gAh + c*8);
            cp16(sb + TILE_B + sw, gWh + c*8);
        }
        cp_commit();
    };

    float acc[4][4][4];
    #pragma unroll
    for (int i = 0; i < 4; i++)
        #pragma unroll
        for (int j = 0; j < 4; j++)
            #pragma unroll
            for (int t = 0; t < 4; t++) acc[i][j][t] = 0.0f;

    uint32_t aRowBase[4]; int aKey[4];
    #pragma unroll
    for (int mi = 0; mi < 4; mi++) {
        int row = wm + mi*16 + ((sub & 1) << 3) + r8;
        aRowBase[mi] = row * 128;
        aKey[mi] = row & 7;
    }
    const int aChunkOff = sub >> 1;
    uint32_t bRowBase[2]; int bKey[2];
    #pragma unroll
    for (int pr = 0; pr < 2; pr++) {
        int row = wn + pr*16 + ((sub >> 1) << 3) + r8;
        bRowBase[pr] = row * 128;
        bKey[pr] = row & 7;
    }
    const int bChunkOff = sub & 1;

    load_stage(0, 0);
    load_stage(1, 1);

    for (int kt = 0; kt < nt; kt++) {
        if (kt + 1 < nt) cp_wait<1>(); else cp_wait<0>();
        __syncthreads();
        if (kt + 2 < nt) load_stage(kt + 2, (kt + 2) % NSTAGE);

        uint32_t sb = smb + (kt % NSTAGE) * STB;

        #pragma unroll
        for (int kk = 0; kk < 4; kk++) {
            uint32_t Bh[2][4];
            #pragma unroll
            for (int pr = 0; pr < 2; pr++) {
                int chunk = kk*2 + bChunkOff;
                uint32_t ad = sb + TILE_B + bRowBase[pr]
                            + (uint32_t)((chunk ^ bKey[pr]) << 4);
                ldsm4(ad, Bh[pr][0], Bh[pr][1], Bh[pr][2], Bh[pr][3]);
            }
            #pragma unroll
            for (int mi = 0; mi < 4; mi++) {
                int chunk = kk*2 + aChunkOff;
                uint32_t ad = sb + aRowBase[mi]
                            + (uint32_t)((chunk ^ aKey[mi]) << 4);
                uint32_t Af[4];
                ldsm4(ad, Af[0], Af[1], Af[2], Af[3]);
                #pragma unroll
                for (int ni = 0; ni < 4; ni++) {
                    int pr = ni >> 1, half = (ni & 1) * 2;
                    mma16816(acc[mi][ni], Af, &Bh[pr][half]);
                }
            }
        }
    }

    // ---- epilogue: vectorized (float2 / half2) ----
    int r4 = lane >> 2, c2 = (lane & 3) * 2;
    #pragma unroll
    for (int mi = 0; mi < 4; mi++) {
        #pragma unroll
        for (int hh = 0; hh < 2; hh++) {
            int m = bm + wm + mi*16 + r4 + hh*8;
            if (m >= M) continue;
            #pragma unroll
            for (int ni = 0; ni < 4; ni++) {
                int n0 = bn + wn + ni*8 + c2;
                float v0 = acc[mi][ni][hh*2 + 0];
                float v1 = acc[mi][ni][hh*2 + 1];
                size_t idx = (size_t)m * N + n0;
                if (EPI != 0) {
                    float2 bb = *(const float2*)&bias[n0];
                    v0 += bb.x; v1 += bb.y;
                }
                if (EPI == 1) {
                    float2 rr = *(const float2*)&res[idx];
                    v0 += rr.x; v1 += rr.y;
                }
                if (EPI == 2) {
                    v0 = 0.5f * v0 * (1.0f + erff(v0 * 0.7071067811865476f));
                    v1 = 0.5f * v1 * (1.0f + erff(v1 * 0.7071067811865476f));
                }
                if (OUTM == 0) *(float2*)&Cf[idx] = make_float2(v0, v1);
                else           *(uint32_t*)&Ch[idx] = pack2h(v0, v1);
            }
        }
    }
}

// ---------------- cls attention, split-K partials (coalesced QK, exp2 domain) ---
__global__ void __launch_bounds__(256) cls_attn_part(const __half* __restrict__ qkvh,
                                                     float* __restrict__ part)
{
    __shared__ float sq[64];
    __shared__ float sc[CHUNK];
    __shared__ float red[256];
    __shared__ float so[4][64];

    int bh = blockIdx.x, sp = blockIdx.y;
    int b = bh / HH, h = bh % HH;
    int tid = threadIdx.x;
    int lane = tid & 31, wid = tid >> 5;
    int i0 = sp * CHUNK;
    int i1 = i0 + CHUNK; if (i1 > NN) i1 = NN;
    int cnt = i1 - i0;

    const __half* qbase = qkvh + (size_t)(b * NN) * (3*CC) + h * HD;
    if (tid < 64) sq[tid] = __half2float(qbase[tid]);
    __syncthreads();

    const int g = lane >> 3;
    const int s8 = lane & 7;
    float qf[8];
    #pragma unroll
    for (int i = 0; i < 8; i++) qf[i] = sq[s8 * 8 + i];

    float lmax = -1e30f;
    for (int base = 0; base < cnt; base += 32) {
        int j = base + wid * 4 + g;
        float dot = 0.0f;
        if (j < cnt) {
            const uint4* kr = (const uint4*)(qkvh + (size_t)(b * NN + i0 + j) * (3*CC) + CC + h * HD);
            uint4 kv = kr[s8];
            __half2 h0 = *(__half2*)&kv.x, h1v = *(__half2*)&kv.y;
            __half2 h2 = *(__half2*)&kv.z, h3 = *(__half2*)&kv.w;
            float2 f0 = __half22float2(h0), f1 = __half22float2(h1v);
            float2 f2 = __half22float2(h2), f3 = __half22float2(h3);
            dot = qf[0]*f0.x + qf[1]*f0.y + qf[2]*f1.x + qf[3]*f1.y
                + qf[4]*f2.x + qf[5]*f2.y + qf[6]*f3.x + qf[7]*f3.y;
        }
        dot += __shfl_xor_sync(0xffffffffu, dot, 1);
        dot += __shfl_xor_sync(0xffffffffu, dot, 2);
        dot += __shfl_xor_sync(0xffffffffu, dot, 4);
        if (s8 == 0 && j < cnt) {
            float sv = dot * SCALE2;
            sc[j] = sv;
            lmax = fmaxf(lmax, sv);
        }
    }
    red[tid] = lmax; __syncthreads();
    for (int off = 128; off; off >>= 1) {
        if (tid < off) red[tid] = fmaxf(red[tid], red[tid + off]);
        __syncthreads();
    }
    float m = red[0];
    __syncthreads();

    float lsum = 0.0f;
    for (int j = tid; j < cnt; j += 256) {
        float e = exp2f(sc[j] - m);
        sc[j] = e;
        lsum += e;
    }
    red[tid] = lsum; __syncthreads();
    for (int off = 128; off; off >>= 1) {
        if (tid < off) red[tid] += red[tid + off];
        __syncthreads();
    }
    float l = red[0];
    __syncthreads();

    int d = tid & 63, p = tid >> 6;
    float o = 0.0f;
    for (int j = p; j < cnt; j += 4)
        o = fmaf(sc[j], __half2float(qkvh[(size_t)(b * NN + i0 + j) * (3*CC) + 2*CC + h * HD + d]), o);
    so[p][d] = o;
    __syncthreads();

    float* pr = part + (size_t)(bh * NSPLIT + sp) * 80;
    if (tid == 0) { pr[0] = m; pr[1] = l; }
    if (tid < 64) pr[2 + tid] = so[0][tid] + so[1][tid] + so[2][tid] + so[3][tid];
}

// ---------------- cls attention reduce (exp2 domain, 2 bh per block) -----------
__global__ void __launch_bounds__(128) cls_attn_reduce(const float* __restrict__ part,
                                                       const float* __restrict__ h1,
                                                       float* __restrict__ cls,
                                                       __half* __restrict__ yh)
{
    int bh = blockIdx.x * 2 + (threadIdx.x >> 6);
    int b = bh / HH, h = bh % HH;
    int d = threadIdx.x & 63;

    const float* pr = part + (size_t)bh * NSPLIT * 80;
    float m = -1e30f;
    #pragma unroll
    for (int s = 0; s < NSPLIT; s++) m = fmaxf(m, pr[s*80]);
    float l = 0.0f, o = 0.0f;
    #pragma unroll
    for (int s = 0; s < NSPLIT; s++) {
        float w = exp2f(pr[s*80] - m);
        l += w * pr[s*80 + 1];
        o += w * pr[s*80 + 2 + d];
    }
    float val = o / l;
    size_t off0 = (size_t)(b * NN) * CC + h * HD + d;
    float v = val + h1[off0];
    cls[b * CC + h * HD + d] = v;
    yh[off0] = __float2half_rn(v);
}

// ---------------- cls qkv (fp16 weights, vectorized) ----------------
__global__ void __launch_bounds__(256) cls_qkv_kernel(const float* __restrict__ cls,
                                                      const __half* __restrict__ wqh,
                                                      __half* __restrict__ qkvch)
{
    int j = blockIdx.x;
    int w = threadIdx.x >> 5;
    int lane = threadIdx.x & 31;
    const float2* cr = (const float2*)(cls + (size_t)w * CC);
    const __half2* wr = (const __half2*)(wqh + (size_t)j * CC);
    float s = 0.0f;
    #pragma unroll 4
    for (int k = lane; k < CC/2; k += 32) {
        float2 c = cr[k];
        float2 wv = __half22float2(wr[k]);
        s = fmaf(c.x, wv.x, s);
        s = fmaf(c.y, wv.y, s);
    }
    #pragma unroll
    for (int off = 16; off; off >>= 1) s += __shfl_xor_sync(0xffffffffu, s, off);
    if (lane == 0) qkvch[w * (3*CC) + j] = __float2half_rn(s);
}

// ---------------- branch attention: 128-query tiles, 8 warps, 3-buffer KV ring ----
// smem: Q 16KB + 3 x 16KB KV = 64KB. grid (4, NBB, 96) = 1536 CTAs.
#define BQ   0
#define BKV  16384

__global__ void __launch_bounds__(256) branch_attn_kernel(
    const __half* __restrict__ qkvh, const __half* __restrict__ qkvch,
    __half* __restrict__ yh)
{
    extern __shared__ char dynraw[];
    uint32_t raw = smem_u32(dynraw);
    uint32_t smb = (raw + 127) & ~127u;

    const int tid = threadIdx.x;
    const int lane = tid & 31, wid = tid >> 5;
    const int r8 = lane & 7, sub = lane >> 3;
    const int qt = blockIdx.x, nb = blockIdx.y;
    const int b = blockIdx.z / HH, h = blockIdx.z % HH;

    const int kr = tid >> 2;
    const int kch0 = (tid & 3) * 2;
    const uint32_t kro = kr * 128;

    auto load_kv = [&](int kt, int buf) {
        int jg = kt * 64 + kr;
        int jc = jg > 512 ? 512 : jg;
        const __half *kh_s, *vh_s;
        if (jc == 0) {
            size_t rb = (size_t)b * (3*CC) + h * HD;
            kh_s = qkvch + rb + CC;
            vh_s = qkvch + rb + 2*CC;
        } else {
            int token = nb * SPB + jc;
            size_t rb = (size_t)(b * NN + token) * (3*CC) + h * HD;
            kh_s = qkvh + rb + CC;
            vh_s = qkvh + rb + 2*CC;
        }
        uint32_t bk = smb + BKV + buf * 16384;
        uint32_t bv = bk + 8192;
        #pragma unroll
        for (int c = 0; c < 2; c++) {
            int chunk = kch0 + c;
            uint32_t sw = kro + (uint32_t)((chunk ^ (kr & 7)) << 4);
            cp16(bk + sw, kh_s + chunk*8);
            cp16(bv + sw, vh_s + chunk*8);
        }
        cp_commit();
    };

    {
        int qrow = tid >> 1;
        int ch0 = (tid & 1) * 4;
        int token = 1 + nb * SPB + qt * 128 + qrow;
        const __half* gh = qkvh + (size_t)(b * NN + token) * (3*CC) + h * HD;
        uint32_t ro = qrow * 128;
        #pragma unroll
        for (int c = 0; c < 4; c++) {
            int chunk = ch0 + c;
            uint32_t sw = ro + (uint32_t)((chunk ^ (qrow & 7)) << 4);
            cp16(smb + BQ + sw, gh + chunk*8);
        }
        cp_commit();
    }
    load_kv(0, 0);
    load_kv(1, 1);

    float m0 = -1e30f, m1 = -1e30f, l0 = 0.0f, l1 = 0.0f;
    float oreg[8][4];
    #pragma unroll
    for (int i = 0; i < 8; i++)
        #pragma unroll
        for (int t = 0; t < 4; t++) oreg[i][t] = 0.0f;

    for (int kt = 0; kt < 9; kt++) {
        if (kt < 8) cp_wait<1>(); else cp_wait<0>();
        __syncthreads();
        if (kt + 2 < 9) load_kv(kt + 2, (kt + 2) % 3);

        uint32_t bk = smb + BKV + (kt % 3) * 16384;
        uint32_t bv = bk + 8192;

        // ---- S = Q K^T ----
        float sreg[8][4];
        #pragma unroll
        for (int i = 0; i < 8; i++)
            #pragma unroll
            for (int t = 0; t < 4; t++) sreg[i][t] = 0.0f;

        #pragma unroll
        for (int kk = 0; kk < 4; kk++) {
            int arow = wid*16 + ((sub & 1) << 3) + r8;
            uint32_t aad = smb + BQ + arow*128
                         + (uint32_t)(((kk*2 + (sub >> 1)) ^ (arow & 7)) << 4);
            uint32_t qh[4];
            ldsm4(aad, qh[0], qh[1], qh[2], qh[3]);
            #pragma unroll
            for (int pr = 0; pr < 4; pr++) {
                int brow = pr*16 + ((sub >> 1) << 3) + r8;
                uint32_t bad = bk + brow*128
                             + (uint32_t)(((kk*2 + (sub & 1)) ^ (brow & 7)) << 4);
                uint32_t kh[4];
                ldsm4(bad, kh[0], kh[1], kh[2], kh[3]);
                mma16816(sreg[pr*2    ], qh, &kh[0]);
                mma16816(sreg[pr*2 + 1], qh, &kh[2]);
            }
        }

        // ---- scale (log2 domain) + mask ----
        #pragma unroll
        for (int nt = 0; nt < 8; nt++)
            #pragma unroll
            for (int t = 0; t < 4; t++) {
                float v = sreg[nt][t] * SCALE2;
                int gcol = kt*64 + nt*8 + (lane & 3)*2 + (t & 1);
                if (gcol > 512) v = -1e30f;
                sreg[nt][t] = v;
            }

        float mt0 = -1e30f, mt1 = -1e30f;
        #pragma unroll
        for (int nt = 0; nt < 8; nt++) {
            mt0 = fmaxf(mt0, fmaxf(sreg[nt][0], sreg[nt][1]));
            mt1 = fmaxf(mt1, fmaxf(sreg[nt][2], sreg[nt][3]));
        }
        mt0 = fmaxf(mt0, __shfl_xor_sync(0xffffffffu, mt0, 1));
        mt0 = fmaxf(mt0, __shfl_xor_sync(0xffffffffu, mt0, 2));
        mt1 = fmaxf(mt1, __shfl_xor_sync(0xffffffffu, mt1, 1));
        mt1 = fmaxf(mt1, __shfl_xor_sync(0xffffffffu, mt1, 2));
        float mn0 = fmaxf(m0, mt0), mn1 = fmaxf(m1, mt1);
        float a0 = exp2f(m0 - mn0), a1 = exp2f(m1 - mn1);
        m0 = mn0; m1 = mn1;
        float rs0 = 0.0f, rs1 = 0.0f;
        #pragma unroll
        for (int nt = 0; nt < 8; nt++) {
            sreg[nt][0] = exp2f(sreg[nt][0] - mn0);
            sreg[nt][1] = exp2f(sreg[nt][1] - mn0);
            sreg[nt][2] = exp2f(sreg[nt][2] - mn1);
            sreg[nt][3] = exp2f(sreg[nt][3] - mn1);
            rs0 += sreg[nt][0] + sreg[nt][1];
            rs1 += sreg[nt][2] + sreg[nt][3];
        }
        rs0 += __shfl_xor_sync(0xffffffffu, rs0, 1);
        rs0 += __shfl_xor_sync(0xffffffffu, rs0, 2);
        rs1 += __shfl_xor_sync(0xffffffffu, rs1, 1);
        rs1 += __shfl_xor_sync(0xffffffffu, rs1, 2);
        l0 = l0 * a0 + rs0;
        l1 = l1 * a1 + rs1;
        #pragma unroll
        for (int dt = 0; dt < 8; dt++) {
            oreg[dt][0] *= a0; oreg[dt][1] *= a0;
            oreg[dt][2] *= a1; oreg[dt][3] *= a1;
        }

        uint32_t ph[4][4];
        #pragma unroll
        for (int kc = 0; kc < 4; kc++) {
            ph[kc][0] = pack2h(sreg[2*kc][0],   sreg[2*kc][1]);
            ph[kc][1] = pack2h(sreg[2*kc][2],   sreg[2*kc][3]);
            ph[kc][2] = pack2h(sreg[2*kc+1][0], sreg[2*kc+1][1]);
            ph[kc][3] = pack2h(sreg[2*kc+1][2], sreg[2*kc+1][3]);
        }

        #pragma unroll
        for (int kc = 0; kc < 4; kc++) {
            #pragma unroll
            for (int dg = 0; dg < 4; dg++) {
                int vrow = kc*16 + ((sub & 1) << 3) + r8;
                uint32_t vad = bv + vrow*128
                             + (uint32_t)(((dg*2 + (sub >> 1)) ^ (vrow & 7)) << 4);
                uint32_t vh[4];
                ldsm4t(vad, vh[0], vh[1], vh[2], vh[3]);
                mma16816(oreg[dg*2    ], ph[kc], &vh[0]);
                mma16816(oreg[dg*2 + 1], ph[kc], &vh[2]);
            }
        }
    }

    // ---- write out (scrambled reshape, half2-paired stores) ----
    float inv0 = 1.0f / l0, inv1 = 1.0f / l1;
    int r4 = lane >> 2, c2 = (lane & 3) * 2;
    #pragma unroll
    for (int dt = 0; dt < 8; dt++) {
        #pragma unroll
        for (int rh = 0; rh < 2; rh++) {
            int sp = qt*128 + wid*16 + r4 + rh*8;
            int dp = dt*8 + c2;
            float inv = rh ? inv1 : inv0;
            float v0 = oreg[dt][rh*2 + 0] * inv;
            float v1 = oreg[dt][rh*2 + 1] * inv;
            int linear = h * (SPB * HD) + sp * HD + dp;   // even
            int s_ = linear / CC;
            int c = linear - s_ * CC;
            int token = 1 + nb * SPB + s_;
            *(uint32_t*)&yh[(size_t)(b * NN + token) * CC + c] = pack2h(v0, v1);
        }
    }
}

// ---------------- launch ----------------
extern "C" void kernel_launch(void* const* d_in, const int* in_sizes, int n_in,
                              void* d_out, int out_size)
{
    const float* x      = (const float*)d_in[0];
    const float* ln1_w  = (const float*)d_in[1];
    const float* ln1_b  = (const float*)d_in[2];
    const float* qkv_w  = (const float*)d_in[3];
    const float* proj_w = (const float*)d_in[4];
    const float* proj_b = (const float*)d_in[5];
    const float* ln2_w  = (const float*)d_in[6];
    const float* ln2_b  = (const float*)d_in[7];
    const float* fc1_w  = (const float*)d_in[8];
    const float* fc1_b  = (const float*)d_in[9];
    const float* fc2_w  = (const float*)d_in[10];
    const float* fc2_b  = (const float*)d_in[11];
    float* out = (float*)d_out;

    float *h1f, *cls, *clsp, *x2;
    __half *h1h, *qkvh, *qkvch, *yh, *h2h, *f1h;
    __half *wqh, *wph, *w1h, *w2h;
    cudaGetSymbolAddress((void**)&h1f,   g_h1f);
    cudaGetSymbolAddress((void**)&h1h,   g_h1h);
    cudaGetSymbolAddress((void**)&qkvh,  g_qkvh);
    cudaGetSymbolAddress((void**)&qkvch, g_qkvch);
    cudaGetSymbolAddress((void**)&cls,   g_cls);
    cudaGetSymbolAddress((void**)&clsp,  g_clsp);
    cudaGetSymbolAddress((void**)&yh,    g_yh);
    cudaGetSymbolAddress((void**)&x2,    g_x2);
    cudaGetSymbolAddress((void**)&h2h,   g_h2h);
    cudaGetSymbolAddress((void**)&f1h,   g_f1h);
    cudaGetSymbolAddress((void**)&wqh,   g_wqh);
    cudaGetSymbolAddress((void**)&wph,   g_wph);
    cudaGetSymbolAddress((void**)&w1h,   g_w1h);
    cudaGetSymbolAddress((void**)&w2h,   g_w2h);

    const int M = MROWS;
    const int smem1 = NSTAGE * 2 * TILE_B + 128;   // 98432
    cudaFuncSetAttribute(tc_gemm<0,3>, cudaFuncAttributeMaxDynamicSharedMemorySize, smem1);
    cudaFuncSetAttribute(tc_gemm<1,0>, cudaFuncAttributeMaxDynamicSharedMemorySize, smem1);
    cudaFuncSetAttribute(tc_gemm<2,3>, cudaFuncAttributeMaxDynamicSharedMemorySize, smem1);
    const int ba_smem = 16384 + 3*16384 + 128;     // Q(128) + 3x(K,V) = 64KB+pad
    cudaFuncSetAttribute(branch_attn_kernel, cudaFuncAttributeMaxDynamicSharedMemorySize, ba_smem);

    // 0+1. prologue: LN1 blocks + all weight converts, ONE launch
    {
        int ln_blocks = (M + 7) / 8;               // 2049
        int nb0 = 3*CC*CC/4/256;                   // 1728
        int nb1 = CC*CC/4/256;                     // 576
        int nb2 = 4*CC*CC/4/256;                   // 2304
        int nb3 = nb2;
        int c1 = nb0, c2 = nb0+nb1, c3 = nb0+nb1+nb2;
        prologue_kernel<<<ln_blocks + c3 + nb3, 256>>>(
            x, ln1_w, ln1_b, h1f, h1h, ln_blocks,
            qkv_w, proj_w, fc1_w, fc2_w, wqh, wph, w1h, w2h, c1, c2, c3);
    }

    // 2. qkv = h1 @ qkv_w^T  (fp16 out)
    {
        dim3 grid((3*CC)/128, MPAD/128);
        tc_gemm<0,3><<<grid, 256, smem1>>>(h1h, wqh, nullptr, nullptr,
                                           nullptr, qkvh, M, 3*CC, CC);
    }

    // 3. cls global attention (split-K partials + reduce)
    {
        dim3 grid(BB*HH, NSPLIT);
        cls_attn_part<<<grid, 256>>>(qkvh, clsp);
        cls_attn_reduce<<<BB*HH/2, 128>>>(clsp, h1f, cls, yh);
    }

    // 4. cls qkv (fp16 weights)
    cls_qkv_kernel<<<3*CC, 256>>>(cls, wqh, qkvch);

    // 5. branch attention (128-query tiles)
    {
        dim3 grid(4, NBB, BB*HH);
        branch_attn_kernel<<<grid, 256, ba_smem>>>(qkvh, qkvch, yh);
    }

    // 6. x2 = x + y @ proj_w^T + proj_b
    {
        dim3 grid(CC/128, MPAD/128);
        tc_gemm<1,0><<<grid, 256, smem1>>>(yh, wph, proj_b, x,
                                           x2, nullptr, M, CC, CC);
    }

    // 7. LN2 (fp16 out)
    ln_kernel<<<(M + 7)/8, 256>>>(x2, ln2_w, ln2_b, h2h, M);

    // 8. fc1 + gelu (fp16 out)
    {
        dim3 grid((4*CC)/128, MPAD/128);
        tc_gemm<2,3><<<grid, 256, smem1>>>(h2h, w1h, fc1_b, nullptr,
                                           nullptr, f1h, M, 4*CC, CC);
    }

    // 9. out = x2 + fc1g @ fc2_w^T + fc2_b
    {
        dim3 grid(CC/128, MPAD/128);
        tc_gemm<1,0><<<grid, 256, smem1>>>(f1h, w2h, fc2_b, x2,
                                           out, nullptr, M, CC, 4*CC);
    }
}

// round 17
// speedup vs baseline: 1.0196x; 1.0036x over previous
#include <cuda_runtime.h>
#include <cuda_fp16.h>
#include <math.h>
#include <stdint.h>

// ---------------- problem constants ----------------
#define BB   8
#define NN   2049
#define CC   768
#define HH   12
#define NBB  4
#define HD   64
#define SPB  512
#define MROWS (BB*NN)      // 16392
#define MPAD  16512        // 129 * 128
#define SCALE 0.125f
#define SCALE2 0.18033688011112042f   // SCALE * log2(e)
#define LNEPS 1e-6f
#define NSPLIT 16
#define CHUNK 129          // ceil(2049/16)

// ---------------- scratch ----------------
__device__ float g_h1f [(size_t)MROWS * CC];       // only cls rows written/read
__device__ __half g_h1h[(size_t)MPAD * CC];
__device__ __half g_qkvh[(size_t)MROWS * 3 * CC];
__device__ __half g_qkvch[BB * 3 * CC];
__device__ float g_cls [BB * CC];
__device__ float g_clsp[BB * HH * NSPLIT * 80];    // partial m,l,o[64]
__device__ __half g_yh [(size_t)MPAD * CC];
__device__ float g_x2  [(size_t)MROWS * CC];
__device__ __half g_h2h[(size_t)MPAD * CC];
__device__ __half g_f1h[(size_t)MPAD * 4 * CC];
__device__ __half g_wqh[3*CC*CC];
__device__ __half g_wph[CC*CC];
__device__ __half g_w1h[4*CC*CC];
__device__ __half g_w2h[4*CC*CC];

// ---------------- helpers ----------------
__device__ __forceinline__ uint32_t smem_u32(const void* p) {
    return (uint32_t)__cvta_generic_to_shared(p);
}
__device__ __forceinline__ void cp16(uint32_t saddr, const void* g) {
    asm volatile("cp.async.cg.shared.global [%0], [%1], 16;\n" :: "r"(saddr), "l"(g));
}
__device__ __forceinline__ void cp_commit() { asm volatile("cp.async.commit_group;\n"); }
template<int NW> __device__ __forceinline__ void cp_wait() {
    asm volatile("cp.async.wait_group %0;\n" :: "n"(NW));
}
__device__ __forceinline__ void ldsm4(uint32_t addr, uint32_t& r0, uint32_t& r1,
                                      uint32_t& r2, uint32_t& r3) {
    asm volatile("ldmatrix.sync.aligned.m8n8.x4.shared.b16 {%0,%1,%2,%3}, [%4];"
                 : "=r"(r0), "=r"(r1), "=r"(r2), "=r"(r3) : "r"(addr));
}
__device__ __forceinline__ void ldsm4t(uint32_t addr, uint32_t& r0, uint32_t& r1,
                                       uint32_t& r2, uint32_t& r3) {
    asm volatile("ldmatrix.sync.aligned.m8n8.x4.trans.shared.b16 {%0,%1,%2,%3}, [%4];"
                 : "=r"(r0), "=r"(r1), "=r"(r2), "=r"(r3) : "r"(addr));
}
__device__ __forceinline__ void mma16816(float* c, const uint32_t* a, const uint32_t* b) {
    asm volatile("mma.sync.aligned.m16n8k16.row.col.f32.f16.f16.f32 "
        "{%0,%1,%2,%3}, {%4,%5,%6,%7}, {%8,%9}, {%0,%1,%2,%3};"
        : "+f"(c[0]), "+f"(c[1]), "+f"(c[2]), "+f"(c[3])
        : "r"(a[0]), "r"(a[1]), "r"(a[2]), "r"(a[3]), "r"(b[0]), "r"(b[1]));
}
__device__ __forceinline__ uint32_t pack2h(float a, float b) {
    __half2 h = __float22half2_rn(make_float2(a, b));
    return *(uint32_t*)&h;
}
__device__ __forceinline__ void cvt4(const float* __restrict__ in,
                                     __half* __restrict__ oh, int i)
{
    float4 v = ((const float4*)in)[i];
    uint2 o;
    o.x = pack2h(v.x, v.y);
    o.y = pack2h(v.z, v.w);
    ((uint2*)oh)[i] = o;
}

// ---------------- LN row body (warp-collective) ----------------
__device__ __forceinline__ void ln_row(const float* __restrict__ x,
                                       const float* __restrict__ w,
                                       const float* __restrict__ b,
                                       float* __restrict__ outf,
                                       __half* __restrict__ oh,
                                       int row, int lane)
{
    const float4* xr = (const float4*)(x + (size_t)row * CC);

    float4 v[6];
    float s = 0.0f;
    #pragma unroll
    for (int i = 0; i < 6; i++) {
        v[i] = xr[i * 32 + lane];
        s += v[i].x + v[i].y + v[i].z + v[i].w;
    }
    #pragma unroll
    for (int o = 16; o; o >>= 1) s += __shfl_xor_sync(0xffffffffu, s, o);
    float mu = s * (1.0f / CC);

    float q = 0.0f;
    #pragma unroll
    for (int i = 0; i < 6; i++) {
        v[i].x -= mu; v[i].y -= mu; v[i].z -= mu; v[i].w -= mu;
        q += v[i].x*v[i].x + v[i].y*v[i].y + v[i].z*v[i].z + v[i].w*v[i].w;
    }
    #pragma unroll
    for (int o = 16; o; o >>= 1) q += __shfl_xor_sync(0xffffffffu, q, o);
    float rs = rsqrtf(q * (1.0f / CC) + LNEPS);

    const float4* w4 = (const float4*)w;
    const float4* b4 = (const float4*)b;
    uint2* oh2 = (uint2*)(oh + (size_t)row * CC);
    bool wf = (outf != nullptr) && (row % NN) == 0;
    float4* of4 = wf ? (float4*)(outf + (size_t)row * CC) : nullptr;

    #pragma unroll
    for (int i = 0; i < 6; i++) {
        float4 wv = w4[i * 32 + lane], bv = b4[i * 32 + lane];
        float o0 = v[i].x * rs * wv.x + bv.x;
        float o1 = v[i].y * rs * wv.y + bv.y;
        float o2 = v[i].z * rs * wv.z + bv.z;
        float o3 = v[i].w * rs * wv.w + bv.w;
        oh2[i * 32 + lane] = make_uint2(pack2h(o0, o1), pack2h(o2, o3));
        if (wf) of4[i * 32 + lane] = make_float4(o0, o1, o2, o3);
    }
}

// ---------------- prologue: LN1 blocks + qkv-weight convert only ----------------
__global__ void __launch_bounds__(256) prologue_kernel(
    const float* __restrict__ x, const float* __restrict__ ln1_w,
    const float* __restrict__ ln1_b, float* __restrict__ h1f,
    __half* __restrict__ h1h, int ln_blocks,
    const float* __restrict__ qkv_w, __half* __restrict__ wqh)
{
    int bi = blockIdx.x;
    if (bi < ln_blocks) {
        int row = bi * 8 + (threadIdx.x >> 5);
        if (row < MROWS)
            ln_row(x, ln1_w, ln1_b, h1f, h1h, row, threadIdx.x & 31);
    } else {
        int i = (bi - ln_blocks) * 256 + threadIdx.x;
        cvt4(qkv_w, wqh, i);
    }
}

// ---------------- LN2 (standalone) ----------------
__global__ void __launch_bounds__(256) ln_kernel(const float* __restrict__ x,
                                                 const float* __restrict__ w,
                                                 const float* __restrict__ b,
                                                 __half* __restrict__ oh,
                                                 int rows)
{
    int row = blockIdx.x * 8 + (threadIdx.x >> 5);
    if (row >= rows) return;
    ln_row(x, w, b, nullptr, oh, row, threadIdx.x & 31);
}

// ================= single-pass fp16 mma.sync GEMM =================
#define TILE_B   16384
#define NSTAGE   3

template<int EPI, int OUTM>
__global__ void __launch_bounds__(256, 2) tc_gemm(
    const __half* __restrict__ Ah, const __half* __restrict__ Wh,
    const float* __restrict__ bias, const float* __restrict__ res,
    float* __restrict__ Cf, __half* __restrict__ Ch,
    int M, int N, int K)
{
    constexpr uint32_t STB = 2 * TILE_B;

    extern __shared__ char dynraw[];
    uint32_t raw = smem_u32(dynraw);
    uint32_t smb = (raw + 127) & ~127u;

    const int tid = threadIdx.x;
    const int bn = blockIdx.x * 128, bm = blockIdx.y * 128;
    const int nt = K >> 6;
    const int lane = tid & 31, wid = tid >> 5;
    const int wm = (wid & 1) * 64, wn = (wid >> 1) * 32;
    const int r8 = lane & 7, sub = lane >> 3;

    const int lrow = tid >> 1;
    const int c0 = (tid & 1) * 4;

    auto load_stage = [&](int kt, int s) {
        uint32_t sb = smb + s * STB;
        size_t goff = (size_t)(kt * 64 + c0 * 8);
        const __half* gAh = Ah + (size_t)(bm + lrow) * K + goff;
        const __half* gWh = Wh + (size_t)(bn + lrow) * K + goff;
        uint32_t ro = lrow * 128;
        #pragma unroll
        for (int c = 0; c < 4; c++) {
            int chunk = c0 + c;
            uint32_t sw = ro + (uint32_t)((chunk ^ (lrow & 7)) << 4);
            cp16(sb          + sw, gAh + c*8);
            cp16(sb + TILE_B + sw, gWh + c*8);
        }
        cp_commit();
    };

    float acc[4][4][4];
    #pragma unroll
    for (int i = 0; i < 4; i++)
        #pragma unroll
        for (int j = 0; j < 4; j++)
            #pragma unroll
            for (int t = 0; t < 4; t++) acc[i][j][t] = 0.0f;

    uint32_t aRowBase[4]; int aKey[4];
    #pragma unroll
    for (int mi = 0; mi < 4; mi++) {
        int row = wm + mi*16 + ((sub & 1) << 3) + r8;
        aRowBase[mi] = row * 128;
        aKey[mi] = row & 7;
    }
    const int aChunkOff = sub >> 1;
    uint32_t bRowBase[2]; int bKey[2];
    #pragma unroll
    for (int pr = 0; pr < 2; pr++) {
        int row = wn + pr*16 + ((sub >> 1) << 3) + r8;
        bRowBase[pr] = row * 128;
        bKey[pr] = row & 7;
    }
    const int bChunkOff = sub & 1;

    load_stage(0, 0);
    load_stage(1, 1);

    for (int kt = 0; kt < nt; kt++) {
        if (kt + 1 < nt) cp_wait<1>(); else cp_wait<0>();
        __syncthreads();
        if (kt + 2 < nt) load_stage(kt + 2, (kt + 2) % NSTAGE);

        uint32_t sb = smb + (kt % NSTAGE) * STB;

        #pragma unroll
        for (int kk = 0; kk < 4; kk++) {
            uint32_t Bh[2][4];
            #pragma unroll
            for (int pr = 0; pr < 2; pr++) {
                int chunk = kk*2 + bChunkOff;
                uint32_t ad = sb + TILE_B + bRowBase[pr]
                            + (uint32_t)((chunk ^ bKey[pr]) << 4);
                ldsm4(ad, Bh[pr][0], Bh[pr][1], Bh[pr][2], Bh[pr][3]);
            }
            #pragma unroll
            for (int mi = 0; mi < 4; mi++) {
                int chunk = kk*2 + aChunkOff;
                uint32_t ad = sb + aRowBase[mi]
                            + (uint32_t)((chunk ^ aKey[mi]) << 4);
                uint32_t Af[4];
                ldsm4(ad, Af[0], Af[1], Af[2], Af[3]);
                #pragma unroll
                for (int ni = 0; ni < 4; ni++) {
                    int pr = ni >> 1, half = (ni & 1) * 2;
                    mma16816(acc[mi][ni], Af, &Bh[pr][half]);
                }
            }
        }
    }

    // ---- epilogue: vectorized (float2 / half2) ----
    int r4 = lane >> 2, c2 = (lane & 3) * 2;
    #pragma unroll
    for (int mi = 0; mi < 4; mi++) {
        #pragma unroll
        for (int hh = 0; hh < 2; hh++) {
            int m = bm + wm + mi*16 + r4 + hh*8;
            if (m >= M) continue;
            #pragma unroll
            for (int ni = 0; ni < 4; ni++) {
                int n0 = bn + wn + ni*8 + c2;
                float v0 = acc[mi][ni][hh*2 + 0];
                float v1 = acc[mi][ni][hh*2 + 1];
                size_t idx = (size_t)m * N + n0;
                if (EPI != 0) {
                    float2 bb = *(const float2*)&bias[n0];
                    v0 += bb.x; v1 += bb.y;
                }
                if (EPI == 1) {
                    float2 rr = *(const float2*)&res[idx];
                    v0 += rr.x; v1 += rr.y;
                }
                if (EPI == 2) {
                    v0 = 0.5f * v0 * (1.0f + erff(v0 * 0.7071067811865476f));
                    v1 = 0.5f * v1 * (1.0f + erff(v1 * 0.7071067811865476f));
                }
                if (OUTM == 0) *(float2*)&Cf[idx] = make_float2(v0, v1);
                else           *(uint32_t*)&Ch[idx] = pack2h(v0, v1);
            }
        }
    }
}

// ---------------- cls attention, split-K partials (coalesced QK, exp2 domain) ---
__global__ void __launch_bounds__(256) cls_attn_part(const __half* __restrict__ qkvh,
                                                     float* __restrict__ part)
{
    __shared__ float sq[64];
    __shared__ float sc[CHUNK];
    __shared__ float red[256];
    __shared__ float so[4][64];

    int bh = blockIdx.x, sp = blockIdx.y;
    int b = bh / HH, h = bh % HH;
    int tid = threadIdx.x;
    int lane = tid & 31, wid = tid >> 5;
    int i0 = sp * CHUNK;
    int i1 = i0 + CHUNK; if (i1 > NN) i1 = NN;
    int cnt = i1 - i0;

    const __half* qbase = qkvh + (size_t)(b * NN) * (3*CC) + h * HD;
    if (tid < 64) sq[tid] = __half2float(qbase[tid]);
    __syncthreads();

    const int g = lane >> 3;
    const int s8 = lane & 7;
    float qf[8];
    #pragma unroll
    for (int i = 0; i < 8; i++) qf[i] = sq[s8 * 8 + i];

    float lmax = -1e30f;
    for (int base = 0; base < cnt; base += 32) {
        int j = base + wid * 4 + g;
        float dot = 0.0f;
        if (j < cnt) {
            const uint4* kr = (const uint4*)(qkvh + (size_t)(b * NN + i0 + j) * (3*CC) + CC + h * HD);
            uint4 kv = kr[s8];
            __half2 h0 = *(__half2*)&kv.x, h1v = *(__half2*)&kv.y;
            __half2 h2 = *(__half2*)&kv.z, h3 = *(__half2*)&kv.w;
            float2 f0 = __half22float2(h0), f1 = __half22float2(h1v);
            float2 f2 = __half22float2(h2), f3 = __half22float2(h3);
            dot = qf[0]*f0.x + qf[1]*f0.y + qf[2]*f1.x + qf[3]*f1.y
                + qf[4]*f2.x + qf[5]*f2.y + qf[6]*f3.x + qf[7]*f3.y;
        }
        dot += __shfl_xor_sync(0xffffffffu, dot, 1);
        dot += __shfl_xor_sync(0xffffffffu, dot, 2);
        dot += __shfl_xor_sync(0xffffffffu, dot, 4);
        if (s8 == 0 && j < cnt) {
            float sv = dot * SCALE2;
            sc[j] = sv;
            lmax = fmaxf(lmax, sv);
        }
    }
    red[tid] = lmax; __syncthreads();
    for (int off = 128; off; off >>= 1) {
        if (tid < off) red[tid] = fmaxf(red[tid], red[tid + off]);
        __syncthreads();
    }
    float m = red[0];
    __syncthreads();

    float lsum = 0.0f;
    for (int j = tid; j < cnt; j += 256) {
        float e = exp2f(sc[j] - m);
        sc[j] = e;
        lsum += e;
    }
    red[tid] = lsum; __syncthreads();
    for (int off = 128; off; off >>= 1) {
        if (tid < off) red[tid] += red[tid + off];
        __syncthreads();
    }
    float l = red[0];
    __syncthreads();

    int d = tid & 63, p = tid >> 6;
    float o = 0.0f;
    for (int j = p; j < cnt; j += 4)
        o = fmaf(sc[j], __half2float(qkvh[(size_t)(b * NN + i0 + j) * (3*CC) + 2*CC + h * HD + d]), o);
    so[p][d] = o;
    __syncthreads();

    float* pr = part + (size_t)(bh * NSPLIT + sp) * 80;
    if (tid == 0) { pr[0] = m; pr[1] = l; }
    if (tid < 64) pr[2 + tid] = so[0][tid] + so[1][tid] + so[2][tid] + so[3][tid];
}

// ---------------- cls attention reduce (exp2 domain, 2 bh per block) -----------
__global__ void __launch_bounds__(128) cls_attn_reduce(const float* __restrict__ part,
                                                       const float* __restrict__ h1,
                                                       float* __restrict__ cls,
                                                       __half* __restrict__ yh)
{
    int bh = blockIdx.x * 2 + (threadIdx.x >> 6);
    int b = bh / HH, h = bh % HH;
    int d = threadIdx.x & 63;

    const float* pr = part + (size_t)bh * NSPLIT * 80;
    float m = -1e30f;
    #pragma unroll
    for (int s = 0; s < NSPLIT; s++) m = fmaxf(m, pr[s*80]);
    float l = 0.0f, o = 0.0f;
    #pragma unroll
    for (int s = 0; s < NSPLIT; s++) {
        float w = exp2f(pr[s*80] - m);
        l += w * pr[s*80 + 1];
        o += w * pr[s*80 + 2 + d];
    }
    float val = o / l;
    size_t off0 = (size_t)(b * NN) * CC + h * HD + d;
    float v = val + h1[off0];
    cls[b * CC + h * HD + d] = v;
    yh[off0] = __float2half_rn(v);
}

// ---------------- cls qkv (fp16 weights, vectorized) ----------------
__global__ void __launch_bounds__(256) cls_qkv_kernel(const float* __restrict__ cls,
                                                      const __half* __restrict__ wqh,
                                                      __half* __restrict__ qkvch)
{
    int j = blockIdx.x;
    int w = threadIdx.x >> 5;
    int lane = threadIdx.x & 31;
    const float2* cr = (const float2*)(cls + (size_t)w * CC);
    const __half2* wr = (const __half2*)(wqh + (size_t)j * CC);
    float s = 0.0f;
    #pragma unroll 4
    for (int k = lane; k < CC/2; k += 32) {
        float2 c = cr[k];
        float2 wv = __half22float2(wr[k]);
        s = fmaf(c.x, wv.x, s);
        s = fmaf(c.y, wv.y, s);
    }
    #pragma unroll
    for (int off = 16; off; off >>= 1) s += __shfl_xor_sync(0xffffffffu, s, off);
    if (lane == 0) qkvch[w * (3*CC) + j] = __float2half_rn(s);
}

// ---------------- branch attention + weight-convert tail blocks ----------------
// blocks [0, 1536): attention (128-query tiles, 8 warps, 3-buffer KV ring, 64KB)
// blocks [1536, 1536+5184): fp32->fp16 weight converts for proj/fc1/fc2
#define BQ   0
#define BKV  16384
#define BA_BLOCKS (4*NBB*BB*HH)   // 1536

__global__ void __launch_bounds__(256) branch_attn_kernel(
    const __half* __restrict__ qkvh, const __half* __restrict__ qkvch,
    __half* __restrict__ yh,
    const float* __restrict__ proj_w, __half* __restrict__ wph,
    const float* __restrict__ fc1_w,  __half* __restrict__ w1h,
    const float* __restrict__ fc2_w,  __half* __restrict__ w2h,
    int cv1, int cv2)
{
    const int bi = blockIdx.x;
    const int tid = threadIdx.x;

    if (bi >= BA_BLOCKS) {
        // ---- weight-convert tail ----
        int cb = bi - BA_BLOCKS;
        if (cb < cv1)      cvt4(proj_w, wph, cb * 256 + tid);
        else if (cb < cv2) cvt4(fc1_w,  w1h, (cb - cv1) * 256 + tid);
        else               cvt4(fc2_w,  w2h, (cb - cv2) * 256 + tid);
        return;
    }

    extern __shared__ char dynraw[];
    uint32_t raw = smem_u32(dynraw);
    uint32_t smb = (raw + 127) & ~127u;

    const int lane = tid & 31, wid = tid >> 5;
    const int r8 = lane & 7, sub = lane >> 3;
    const int qt = bi & 3, nb = (bi >> 2) & 3;
    const int bhz = bi >> 4;
    const int b = bhz / HH, h = bhz % HH;

    const int kr = tid >> 2;
    const int kch0 = (tid & 3) * 2;
    const uint32_t kro = kr * 128;

    auto load_kv = [&](int kt, int buf) {
        int jg = kt * 64 + kr;
        int jc = jg > 512 ? 512 : jg;
        const __half *kh_s, *vh_s;
        if (jc == 0) {
            size_t rb = (size_t)b * (3*CC) + h * HD;
            kh_s = qkvch + rb + CC;
            vh_s = qkvch + rb + 2*CC;
        } else {
            int token = nb * SPB + jc;
            size_t rb = (size_t)(b * NN + token) * (3*CC) + h * HD;
            kh_s = qkvh + rb + CC;
            vh_s = qkvh + rb + 2*CC;
        }
        uint32_t bk = smb + BKV + buf * 16384;
        uint32_t bv = bk + 8192;
        #pragma unroll
        for (int c = 0; c < 2; c++) {
            int chunk = kch0 + c;
            uint32_t sw = kro + (uint32_t)((chunk ^ (kr & 7)) << 4);
            cp16(bk + sw, kh_s + chunk*8);
            cp16(bv + sw, vh_s + chunk*8);
        }
        cp_commit();
    };

    {
        int qrow = tid >> 1;
        int ch0 = (tid & 1) * 4;
        int token = 1 + nb * SPB + qt * 128 + qrow;
        const __half* gh = qkvh + (size_t)(b * NN + token) * (3*CC) + h * HD;
        uint32_t ro = qrow * 128;
        #pragma unroll
        for (int c = 0; c < 4; c++) {
            int chunk = ch0 + c;
            uint32_t sw = ro + (uint32_t)((chunk ^ (qrow & 7)) << 4);
            cp16(smb + BQ + sw, gh + chunk*8);
        }
        cp_commit();
    }
    load_kv(0, 0);
    load_kv(1, 1);

    float m0 = -1e30f, m1 = -1e30f, l0 = 0.0f, l1 = 0.0f;
    float oreg[8][4];
    #pragma unroll
    for (int i = 0; i < 8; i++)
        #pragma unroll
        for (int t = 0; t < 4; t++) oreg[i][t] = 0.0f;

    for (int kt = 0; kt < 9; kt++) {
        if (kt < 8) cp_wait<1>(); else cp_wait<0>();
        __syncthreads();
        if (kt + 2 < 9) load_kv(kt + 2, (kt + 2) % 3);

        uint32_t bk = smb + BKV + (kt % 3) * 16384;
        uint32_t bv = bk + 8192;

        // ---- S = Q K^T ----
        float sreg[8][4];
        #pragma unroll
        for (int i = 0; i < 8; i++)
            #pragma unroll
            for (int t = 0; t < 4; t++) sreg[i][t] = 0.0f;

        #pragma unroll
        for (int kk = 0; kk < 4; kk++) {
            int arow = wid*16 + ((sub & 1) << 3) + r8;
            uint32_t aad = smb + BQ + arow*128
                         + (uint32_t)(((kk*2 + (sub >> 1)) ^ (arow & 7)) << 4);
            uint32_t qh[4];
            ldsm4(aad, qh[0], qh[1], qh[2], qh[3]);
            #pragma unroll
            for (int pr = 0; pr < 4; pr++) {
                int brow = pr*16 + ((sub >> 1) << 3) + r8;
                uint32_t bad = bk + brow*128
                             + (uint32_t)(((kk*2 + (sub & 1)) ^ (brow & 7)) << 4);
                uint32_t kh[4];
                ldsm4(bad, kh[0], kh[1], kh[2], kh[3]);
                mma16816(sreg[pr*2    ], qh, &kh[0]);
                mma16816(sreg[pr*2 + 1], qh, &kh[2]);
            }
        }

        // ---- scale (log2 domain) + mask ----
        #pragma unroll
        for (int nt = 0; nt < 8; nt++)
            #pragma unroll
            for (int t = 0; t < 4; t++) {
                float v = sreg[nt][t] * SCALE2;
                int gcol = kt*64 + nt*8 + (lane & 3)*2 + (t & 1);
                if (gcol > 512) v = -1e30f;
                sreg[nt][t] = v;
            }

        float mt0 = -1e30f, mt1 = -1e30f;
        #pragma unroll
        for (int nt = 0; nt < 8; nt++) {
            mt0 = fmaxf(mt0, fmaxf(sreg[nt][0], sreg[nt][1]));
            mt1 = fmaxf(mt1, fmaxf(sreg[nt][2], sreg[nt][3]));
        }
        mt0 = fmaxf(mt0, __shfl_xor_sync(0xffffffffu, mt0, 1));
        mt0 = fmaxf(mt0, __shfl_xor_sync(0xffffffffu, mt0, 2));
        mt1 = fmaxf(mt1, __shfl_xor_sync(0xffffffffu, mt1, 1));
        mt1 = fmaxf(mt1, __shfl_xor_sync(0xffffffffu, mt1, 2));
        float mn0 = fmaxf(m0, mt0), mn1 = fmaxf(m1, mt1);
        float a0 = exp2f(m0 - mn0), a1 = exp2f(m1 - mn1);
        m0 = mn0; m1 = mn1;
        float rs0 = 0.0f, rs1 = 0.0f;
        #pragma unroll
        for (int nt = 0; nt < 8; nt++) {
            sreg[nt][0] = exp2f(sreg[nt][0] - mn0);
            sreg[nt][1] = exp2f(sreg[nt][1] - mn0);
            sreg[nt][2] = exp2f(sreg[nt][2] - mn1);
            sreg[nt][3] = exp2f(sreg[nt][3] - mn1);
            rs0 += sreg[nt][0] + sreg[nt][1];
            rs1 += sreg[nt][2] + sreg[nt][3];
        }
        rs0 += __shfl_xor_sync(0xffffffffu, rs0, 1);
        rs0 += __shfl_xor_sync(0xffffffffu, rs0, 2);
        rs1 += __shfl_xor_sync(0xffffffffu, rs1, 1);
        rs1 += __shfl_xor_sync(0xffffffffu, rs1, 2);
        l0 = l0 * a0 + rs0;
        l1 = l1 * a1 + rs1;
        #pragma unroll
        for (int dt = 0; dt < 8; dt++) {
            oreg[dt][0] *= a0; oreg[dt][1] *= a0;
            oreg[dt][2] *= a1; oreg[dt][3] *= a1;
        }

        uint32_t ph[4][4];
        #pragma unroll
        for (int kc = 0; kc < 4; kc++) {
            ph[kc][0] = pack2h(sreg[2*kc][0],   sreg[2*kc][1]);
            ph[kc][1] = pack2h(sreg[2*kc][2],   sreg[2*kc][3]);
            ph[kc][2] = pack2h(sreg[2*kc+1][0], sreg[2*kc+1][1]);
            ph[kc][3] = pack2h(sreg[2*kc+1][2], sreg[2*kc+1][3]);
        }

        #pragma unroll
        for (int kc = 0; kc < 4; kc++) {
            #pragma unroll
            for (int dg = 0; dg < 4; dg++) {
                int vrow = kc*16 + ((sub & 1) << 3) + r8;
                uint32_t vad = bv + vrow*128
                             + (uint32_t)(((dg*2 + (sub >> 1)) ^ (vrow & 7)) << 4);
                uint32_t vh[4];
                ldsm4t(vad, vh[0], vh[1], vh[2], vh[3]);
                mma16816(oreg[dg*2    ], ph[kc], &vh[0]);
                mma16816(oreg[dg*2 + 1], ph[kc], &vh[2]);
            }
        }
    }

    // ---- write out (scrambled reshape, half2-paired stores) ----
    float inv0 = 1.0f / l0, inv1 = 1.0f / l1;
    int r4 = lane >> 2, c2 = (lane & 3) * 2;
    #pragma unroll
    for (int dt = 0; dt < 8; dt++) {
        #pragma unroll
        for (int rh = 0; rh < 2; rh++) {
            int sp = qt*128 + wid*16 + r4 + rh*8;
            int dp = dt*8 + c2;
            float inv = rh ? inv1 : inv0;
            float v0 = oreg[dt][rh*2 + 0] * inv;
            float v1 = oreg[dt][rh*2 + 1] * inv;
            int linear = h * (SPB * HD) + sp * HD + dp;   // even
            int s_ = linear / CC;
            int c = linear - s_ * CC;
            int token = 1 + nb * SPB + s_;
            *(uint32_t*)&yh[(size_t)(b * NN + token) * CC + c] = pack2h(v0, v1);
        }
    }
}

// ---------------- launch ----------------
extern "C" void kernel_launch(void* const* d_in, const int* in_sizes, int n_in,
                              void* d_out, int out_size)
{
    const float* x      = (const float*)d_in[0];
    const float* ln1_w  = (const float*)d_in[1];
    const float* ln1_b  = (const float*)d_in[2];
    const float* qkv_w  = (const float*)d_in[3];
    const float* proj_w = (const float*)d_in[4];
    const float* proj_b = (const float*)d_in[5];
    const float* ln2_w  = (const float*)d_in[6];
    const float* ln2_b  = (const float*)d_in[7];
    const float* fc1_w  = (const float*)d_in[8];
    const float* fc1_b  = (const float*)d_in[9];
    const float* fc2_w  = (const float*)d_in[10];
    const float* fc2_b  = (const float*)d_in[11];
    float* out = (float*)d_out;

    float *h1f, *cls, *clsp, *x2;
    __half *h1h, *qkvh, *qkvch, *yh, *h2h, *f1h;
    __half *wqh, *wph, *w1h, *w2h;
    cudaGetSymbolAddress((void**)&h1f,   g_h1f);
    cudaGetSymbolAddress((void**)&h1h,   g_h1h);
    cudaGetSymbolAddress((void**)&qkvh,  g_qkvh);
    cudaGetSymbolAddress((void**)&qkvch, g_qkvch);
    cudaGetSymbolAddress((void**)&cls,   g_cls);
    cudaGetSymbolAddress((void**)&clsp,  g_clsp);
    cudaGetSymbolAddress((void**)&yh,    g_yh);
    cudaGetSymbolAddress((void**)&x2,    g_x2);
    cudaGetSymbolAddress((void**)&h2h,   g_h2h);
    cudaGetSymbolAddress((void**)&f1h,   g_f1h);
    cudaGetSymbolAddress((void**)&wqh,   g_wqh);
    cudaGetSymbolAddress((void**)&wph,   g_wph);
    cudaGetSymbolAddress((void**)&w1h,   g_w1h);
    cudaGetSymbolAddress((void**)&w2h,   g_w2h);

    const int M = MROWS;
    const int smem1 = NSTAGE * 2 * TILE_B + 128;   // 98432
    cudaFuncSetAttribute(tc_gemm<0,3>, cudaFuncAttributeMaxDynamicSharedMemorySize, smem1);
    cudaFuncSetAttribute(tc_gemm<1,0>, cudaFuncAttributeMaxDynamicSharedMemorySize, smem1);
    cudaFuncSetAttribute(tc_gemm<2,3>, cudaFuncAttributeMaxDynamicSharedMemorySize, smem1);
    const int ba_smem = 16384 + 3*16384 + 128;     // Q(128) + 3x(K,V) = 64KB+pad
    cudaFuncSetAttribute(branch_attn_kernel, cudaFuncAttributeMaxDynamicSharedMemorySize, ba_smem);

    // 0+1. prologue: LN1 blocks + qkv-weight convert, ONE launch
    {
        int ln_blocks = (M + 7) / 8;               // 2049
        int wq_blocks = 3*CC*CC/4/256;             // 1728
        prologue_kernel<<<ln_blocks + wq_blocks, 256>>>(
            x, ln1_w, ln1_b, h1f, h1h, ln_blocks, qkv_w, wqh);
    }

    // 2. qkv = h1 @ qkv_w^T  (fp16 out)
    {
        dim3 grid((3*CC)/128, MPAD/128);
        tc_gemm<0,3><<<grid, 256, smem1>>>(h1h, wqh, nullptr, nullptr,
                                           nullptr, qkvh, M, 3*CC, CC);
    }

    // 3. cls global attention (split-K partials + reduce)
    {
        dim3 grid(BB*HH, NSPLIT);
        cls_attn_part<<<grid, 256>>>(qkvh, clsp);
        cls_attn_reduce<<<BB*HH/2, 128>>>(clsp, h1f, cls, yh);
    }

    // 4. cls qkv (fp16 weights)
    cls_qkv_kernel<<<3*CC, 256>>>(cls, wqh, qkvch);

    // 5. branch attention (128-query tiles) + proj/fc weight converts as tail blocks
    {
        int cv1 = CC*CC/4/256;                     // 576  (proj)
        int cv2 = cv1 + 4*CC*CC/4/256;             // +2304 (fc1)
        int cvt_blocks = cv2 + 4*CC*CC/4/256;      // +2304 (fc2) = 5184
        branch_attn_kernel<<<BA_BLOCKS + cvt_blocks, 256, ba_smem>>>(
            qkvh, qkvch, yh, proj_w, wph, fc1_w, w1h, fc2_w, w2h, cv1, cv2);
    }

    // 6. x2 = x + y @ proj_w^T + proj_b
    {
        dim3 grid(CC/128, MPAD/128);
        tc_gemm<1,0><<<grid, 256, smem1>>>(yh, wph, proj_b, x,
                                           x2, nullptr, M, CC, CC);
    }

    // 7. LN2 (fp16 out)
    ln_kernel<<<(M + 7)/8, 256>>>(x2, ln2_w, ln2_b, h2h, M);

    // 8. fc1 + gelu (fp16 out)
    {
        dim3 grid((4*CC)/128, MPAD/128);
        tc_gemm<2,3><<<grid, 256, smem1>>>(h2h, w1h, fc1_b, nullptr,
                                           nullptr, f1h, M, 4*CC, CC);
    }

    // 9. out = x2 + fc1g @ fc2_w^T + fc2_b
    {
        dim3 grid(CC/128, MPAD/128);
        tc_gemm<1,0><<<grid, 256, smem1>>>(f1h, w2h, fc2_b, x2,
                                           out, nullptr, M, CC, 4*CC);
    }
}